// round 1
// baseline (speedup 1.0000x reference)
#include <cuda_runtime.h>
#include <math.h>

#define BB 2
#define NN 65536
#define DD 512
#define MM 128
#define HH 32
#define TILE_N 64
#define CHUNKS (NN / TILE_N)   /* 1024 */
#define NC (MM + HH)           /* 160  */
#define WSTR 36                /* W smem row stride (32 + 4 pad), 16B aligned */
#define LSTR 164               /* logits smem row stride (160 + 4 pad), 16B aligned */

// Deterministic scratch for per-block mode sums (no device-side allocation).
__device__ float g_partials[BB * MM * CHUNKS];

__global__ void __launch_bounds__(256, 1)
fused_kernel(const float* __restrict__ x, const float* __restrict__ mass,
             const float* __restrict__ ln_g, const float* __restrict__ ln_b,
             const float* __restrict__ W_lin, const float* __restrict__ b_lin,
             const float* __restrict__ W_t1, const float* __restrict__ W_t2,
             const float* __restrict__ b_t2, float* __restrict__ out)
{
    extern __shared__ float smf[];
    float* s_nx  = smf;                       // 64*512  = 32768
    float* s_w   = s_nx + TILE_N * DD;        // 160*36  = 5760
    float* s_log = s_w + NC * WSTR;           // 64*164  = 10496
    float* s_g   = s_log + TILE_N * LSTR;     // 512
    float* s_b   = s_g + DD;                  // 512
    float* s_bl  = s_b + DD;                  // 128
    float* s_w2  = s_bl + MM;                 // 32
    float* s_ps  = s_w2 + HH;                 // 8*128 = 1024

    const int tid   = threadIdx.x;
    const int lane  = tid & 31;
    const int warp  = tid >> 5;
    const int b     = blockIdx.x / CHUNKS;
    const int chunk = blockIdx.x % CHUNKS;
    const int n0    = chunk * TILE_N;

    for (int i = tid; i < DD; i += 256) { s_g[i] = ln_g[i]; s_b[i] = ln_b[i]; }
    if (tid < MM) s_bl[tid] = b_lin[tid];
    if (tid < HH) s_w2[tid] = W_t2[tid];
    const float bt2 = b_t2[0];

    __syncthreads();

    // ---------------- Phase A: LayerNorm (warp per row) ----------------
    for (int r = warp; r < TILE_N; r += 8) {
        const float4* xr = reinterpret_cast<const float4*>(
            x + ((size_t)(b * NN + n0 + r)) * DD);
        float4 v[4];
        float s = 0.f, sq = 0.f;
        #pragma unroll
        for (int q = 0; q < 4; q++) {
            v[q] = xr[lane + 32 * q];
            s  += v[q].x + v[q].y + v[q].z + v[q].w;
            sq += v[q].x * v[q].x + v[q].y * v[q].y + v[q].z * v[q].z + v[q].w * v[q].w;
        }
        #pragma unroll
        for (int o = 16; o > 0; o >>= 1) {
            s  += __shfl_xor_sync(0xffffffffu, s,  o);
            sq += __shfl_xor_sync(0xffffffffu, sq, o);
        }
        const float mu   = s * (1.0f / DD);
        const float var  = sq * (1.0f / DD) - mu * mu;
        const float rstd = rsqrtf(var + 1e-5f);
        float4* dst = reinterpret_cast<float4*>(s_nx + r * DD);
        #pragma unroll
        for (int q = 0; q < 4; q++) {
            const int k = (lane + 32 * q) * 4;
            float4 o4;
            o4.x = (v[q].x - mu) * rstd * s_g[k + 0] + s_b[k + 0];
            o4.y = (v[q].y - mu) * rstd * s_g[k + 1] + s_b[k + 1];
            o4.z = (v[q].z - mu) * rstd * s_g[k + 2] + s_b[k + 2];
            o4.w = (v[q].w - mu) * rstd * s_g[k + 3] + s_b[k + 3];
            dst[lane + 32 * q] = o4;
        }
    }

    // ---------------- Phase B: GEMM  C[64x160] = nx[64x512] * W^T --------
    const int ty = tid >> 4;   // 0..15 -> 4 rows each
    const int tx = tid & 15;   // 0..15 -> 10 cols each (tx + 16j)
    float acc[4][10];
    #pragma unroll
    for (int i = 0; i < 4; i++)
        #pragma unroll
        for (int j = 0; j < 10; j++) acc[i][j] = 0.f;

    for (int kt = 0; kt < DD; kt += 32) {
        __syncthreads();   // s_nx ready (first iter) / prev s_w consumed
        #pragma unroll
        for (int i = 0; i < 5; i++) {
            const int idx = tid + i * 256;   // 0..1279 -> 160 rows * 8 quads
            const int row = idx >> 3;
            const int q   = idx & 7;
            const float* src = (row < MM)
                ? (W_lin + (size_t)row * DD + kt)
                : (W_t1 + (size_t)(row - MM) * DD + kt);
            const float4 wv = reinterpret_cast<const float4*>(src)[q];
            reinterpret_cast<float4*>(s_w + row * WSTR)[q] = wv;
        }
        __syncthreads();
        #pragma unroll
        for (int k = 0; k < 32; k += 4) {
            float4 a[4], wv[10];
            #pragma unroll
            for (int i = 0; i < 4; i++)
                a[i] = *reinterpret_cast<const float4*>(s_nx + (ty * 4 + i) * DD + kt + k);
            #pragma unroll
            for (int j = 0; j < 10; j++)
                wv[j] = *reinterpret_cast<const float4*>(s_w + (tx + 16 * j) * WSTR + k);
            #pragma unroll
            for (int i = 0; i < 4; i++) {
                #pragma unroll
                for (int j = 0; j < 10; j++) {
                    acc[i][j] = fmaf(a[i].x, wv[j].x, acc[i][j]);
                    acc[i][j] = fmaf(a[i].y, wv[j].y, acc[i][j]);
                    acc[i][j] = fmaf(a[i].z, wv[j].z, acc[i][j]);
                    acc[i][j] = fmaf(a[i].w, wv[j].w, acc[i][j]);
                }
            }
        }
    }

    // write logits (+ b_lin for mode cols) to smem
    #pragma unroll
    for (int i = 0; i < 4; i++) {
        const int r = ty * 4 + i;
        #pragma unroll
        for (int j = 0; j < 10; j++) {
            const int c = tx + 16 * j;
            s_log[r * LSTR + c] = acc[i][j] + (c < MM ? s_bl[c] : 0.f);
        }
    }
    __syncthreads();

    // ---------------- Phase C/D: temperature + softmax (warp per row) ----
    float4 ps4 = make_float4(0.f, 0.f, 0.f, 0.f);
    for (int r = warp; r < TILE_N; r += 8) {
        float* lr = s_log + r * LSTR;

        // per-point temperature: GELU(exact) -> dot W_t2 -> softplus -> clamp
        const float tval = lr[MM + lane];
        const float gl = 0.5f * tval * (1.0f + erff(tval * 0.7071067811865476f));
        float cacc = gl * s_w2[lane];
        #pragma unroll
        for (int o = 16; o > 0; o >>= 1)
            cacc += __shfl_xor_sync(0xffffffffu, cacc, o);
        const float z   = cacc + bt2;
        const float sp  = (z > 20.f) ? z : log1pf(expf(z));
        const float tau = fminf(fmaxf(sp, 0.01f), 3.0f);
        const float itau = 1.0f / tau;
        const float ms = mass[(size_t)b * NN + n0 + r];

        // softmax over 128 modes (4 per lane)
        float4 l4 = *reinterpret_cast<float4*>(lr + lane * 4);
        l4.x *= itau; l4.y *= itau; l4.z *= itau; l4.w *= itau;
        float mx = fmaxf(fmaxf(l4.x, l4.y), fmaxf(l4.z, l4.w));
        #pragma unroll
        for (int o = 16; o > 0; o >>= 1)
            mx = fmaxf(mx, __shfl_xor_sync(0xffffffffu, mx, o));
        float4 e;
        e.x = expf(l4.x - mx); e.y = expf(l4.y - mx);
        e.z = expf(l4.z - mx); e.w = expf(l4.w - mx);
        float ssum = e.x + e.y + e.z + e.w;
        #pragma unroll
        for (int o = 16; o > 0; o >>= 1)
            ssum += __shfl_xor_sync(0xffffffffu, ssum, o);
        const float inv = 1.0f / ssum;
        float4 p;
        p.x = e.x * inv; p.y = e.y * inv; p.z = e.z * inv; p.w = e.w * inv;

        // trial_func: (B,N,M) coalesced float4 write
        *reinterpret_cast<float4*>(out + ((size_t)b * NN + n0 + r) * MM + lane * 4) = p;

        // trial_in_t values -> back into smem for transpose + partial sums
        float4 pm;
        pm.x = p.x * ms; pm.y = p.y * ms; pm.z = p.z * ms; pm.w = p.w * ms;
        *reinterpret_cast<float4*>(lr + lane * 4) = pm;
        ps4.x += pm.x; ps4.y += pm.y; ps4.z += pm.z; ps4.w += pm.w;
    }

    // deterministic per-warp partial sums (fixed-order combine)
    s_ps[warp * MM + lane * 4 + 0] = ps4.x;
    s_ps[warp * MM + lane * 4 + 1] = ps4.y;
    s_ps[warp * MM + lane * 4 + 2] = ps4.z;
    s_ps[warp * MM + lane * 4 + 3] = ps4.w;
    __syncthreads();

    if (tid < MM) {
        float t = 0.f;
        #pragma unroll
        for (int w = 0; w < 8; w++) t += s_ps[w * MM + tid];
        g_partials[((size_t)b * MM + tid) * CHUNKS + chunk] = t;
    }

    // ---------------- Phase E: transposed coalesced write of trial_in_t --
    const size_t off1 = (size_t)BB * NN * MM;
    #pragma unroll
    for (int it = 0; it < (TILE_N * MM) / 256; it++) {
        const int idx = it * 256 + tid;
        const int m  = idx >> 6;
        const int nl = idx & 63;
        out[off1 + ((size_t)b * MM + m) * NN + n0 + nl] = s_log[nl * LSTR + m];
    }
}

__global__ void norm_kernel(float* __restrict__ out)
{
    __shared__ float red[256];
    const int idx = blockIdx.x;   // b*M + m
    const int tid = threadIdx.x;
    const float* p = g_partials + (size_t)idx * CHUNKS;
    float s = 0.f;
    for (int k = tid; k < CHUNKS; k += 256) s += p[k];
    red[tid] = s;
    __syncthreads();
    for (int o = 128; o > 0; o >>= 1) {
        if (tid < o) red[tid] += red[tid + o];
        __syncthreads();
    }
    if (tid == 0)
        out[(size_t)2 * BB * NN * MM + idx] = 1.0f / (red[0] + 1e-6f);
}

extern "C" void kernel_launch(void* const* d_in, const int* in_sizes, int n_in,
                              void* d_out, int out_size)
{
    const float* x     = (const float*)d_in[0];
    const float* mass  = (const float*)d_in[1];
    const float* ln_g  = (const float*)d_in[2];
    const float* ln_b  = (const float*)d_in[3];
    const float* W_lin = (const float*)d_in[4];
    const float* b_lin = (const float*)d_in[5];
    const float* W_t1  = (const float*)d_in[6];
    const float* W_t2  = (const float*)d_in[7];
    const float* b_t2  = (const float*)d_in[8];
    float* out = (float*)d_out;

    const int smem_bytes =
        (TILE_N * DD + NC * WSTR + TILE_N * LSTR + DD + DD + MM + HH + 8 * MM) * 4;

    cudaFuncSetAttribute(fused_kernel,
                         cudaFuncAttributeMaxDynamicSharedMemorySize, smem_bytes);

    fused_kernel<<<BB * CHUNKS, 256, smem_bytes>>>(
        x, mass, ln_g, ln_b, W_lin, b_lin, W_t1, W_t2, b_t2, out);
    norm_kernel<<<BB * MM, 256>>>(out);
}

// round 2
// speedup vs baseline: 1.1662x; 1.1662x over previous
#include <cuda_runtime.h>
#include <math.h>
#include <stdint.h>

#define BB 2
#define NN 65536
#define DD 512
#define MM 128
#define HH 32
#define TILE_N 64
#define CHUNKS (NN / TILE_N)   /* 1024 */
#define NC (MM + HH)           /* 160  */
#define WSTR 36                /* W smem row stride (32 + 4 pad), 16B aligned */
#define LSTR 164               /* logits smem row stride (160 + 4 pad), 16B aligned */
#define NXSTR 516              /* s_nx row stride: 512 + 4 -> conflict-free mma frag loads */

// Deterministic scratch for per-block mode sums (no device-side allocation).
__device__ float g_partials[BB * MM * CHUNKS];

__device__ __forceinline__ void split_tf32(float a, uint32_t& hi, uint32_t& lo)
{
    asm("cvt.rna.tf32.f32 %0, %1;" : "=r"(hi) : "f"(a));
    float hif = __uint_as_float(hi);
    asm("cvt.rna.tf32.f32 %0, %1;" : "=r"(lo) : "f"(a - hif));
}

__device__ __forceinline__ void mma_tf32(float* c, const uint32_t* a, const uint32_t* b)
{
    asm volatile(
        "mma.sync.aligned.m16n8k8.row.col.f32.tf32.tf32.f32 "
        "{%0,%1,%2,%3}, {%4,%5,%6,%7}, {%8,%9}, {%0,%1,%2,%3};"
        : "+f"(c[0]), "+f"(c[1]), "+f"(c[2]), "+f"(c[3])
        : "r"(a[0]), "r"(a[1]), "r"(a[2]), "r"(a[3]), "r"(b[0]), "r"(b[1]));
}

__global__ void __launch_bounds__(256, 1)
fused_kernel(const float* __restrict__ x, const float* __restrict__ mass,
             const float* __restrict__ ln_g, const float* __restrict__ ln_b,
             const float* __restrict__ W_lin, const float* __restrict__ b_lin,
             const float* __restrict__ W_t1, const float* __restrict__ W_t2,
             const float* __restrict__ b_t2, float* __restrict__ out)
{
    extern __shared__ float smf[];
    float* s_nx  = smf;                       // 64*516  = 33024
    float* s_w   = s_nx + TILE_N * NXSTR;     // 160*36  = 5760
    float* s_log = s_w + NC * WSTR;           // 64*164  = 10496
    float* s_g   = s_log + TILE_N * LSTR;     // 512
    float* s_b   = s_g + DD;                  // 512
    float* s_bl  = s_b + DD;                  // 128
    float* s_w2  = s_bl + MM;                 // 32
    float* s_ps  = s_w2 + HH;                 // 8*128 = 1024

    const int tid   = threadIdx.x;
    const int lane  = tid & 31;
    const int warp  = tid >> 5;
    const int b     = blockIdx.x / CHUNKS;
    const int chunk = blockIdx.x % CHUNKS;
    const int n0    = chunk * TILE_N;

    for (int i = tid; i < DD; i += 256) { s_g[i] = ln_g[i]; s_b[i] = ln_b[i]; }
    if (tid < MM) s_bl[tid] = b_lin[tid];
    if (tid < HH) s_w2[tid] = W_t2[tid];
    const float bt2 = b_t2[0];

    __syncthreads();

    // ---------------- Phase A: LayerNorm (warp per row) ----------------
    for (int r = warp; r < TILE_N; r += 8) {
        const float4* xr = reinterpret_cast<const float4*>(
            x + ((size_t)(b * NN + n0 + r)) * DD);
        float4 v[4];
        float s = 0.f, sq = 0.f;
        #pragma unroll
        for (int q = 0; q < 4; q++) {
            v[q] = xr[lane + 32 * q];
            s  += v[q].x + v[q].y + v[q].z + v[q].w;
            sq += v[q].x * v[q].x + v[q].y * v[q].y + v[q].z * v[q].z + v[q].w * v[q].w;
        }
        #pragma unroll
        for (int o = 16; o > 0; o >>= 1) {
            s  += __shfl_xor_sync(0xffffffffu, s,  o);
            sq += __shfl_xor_sync(0xffffffffu, sq, o);
        }
        const float mu   = s * (1.0f / DD);
        const float var  = sq * (1.0f / DD) - mu * mu;
        const float rstd = rsqrtf(var + 1e-5f);
        float4* dst = reinterpret_cast<float4*>(s_nx + r * NXSTR);
        #pragma unroll
        for (int q = 0; q < 4; q++) {
            const int k = (lane + 32 * q) * 4;
            float4 o4;
            o4.x = (v[q].x - mu) * rstd * s_g[k + 0] + s_b[k + 0];
            o4.y = (v[q].y - mu) * rstd * s_g[k + 1] + s_b[k + 1];
            o4.z = (v[q].z - mu) * rstd * s_g[k + 2] + s_b[k + 2];
            o4.w = (v[q].w - mu) * rstd * s_g[k + 3] + s_b[k + 3];
            dst[lane + 32 * q] = o4;
        }
    }

    // ------------ Phase B: GEMM via mma.sync tf32, 3xTF32 split ---------
    // Block tile 64x160; 8 warps -> warp tile 32x40 (2 m16 frags x 5 n8 frags)
    const int wRow = warp >> 2;           // 0..1  -> rows wRow*32 + [0,32)
    const int wCol = warp & 3;            // 0..3  -> cols wCol*40 + [0,40)
    const int grp  = lane >> 2;           // 0..7
    const int tig  = lane & 3;            // 0..3

    float acc[2][5][4];
    #pragma unroll
    for (int i = 0; i < 2; i++)
        #pragma unroll
        for (int j = 0; j < 5; j++)
            #pragma unroll
            for (int q = 0; q < 4; q++) acc[i][j][q] = 0.f;

    const float* a_base = s_nx + (wRow * 32 + grp) * NXSTR + tig;
    const float* b_base = s_w + (wCol * 40 + grp) * WSTR + tig;

    for (int kt = 0; kt < DD; kt += 32) {
        __syncthreads();   // s_nx ready (first iter) / prev s_w consumed
        #pragma unroll
        for (int i = 0; i < 5; i++) {
            const int idx = tid + i * 256;   // 0..1279 -> 160 rows * 8 quads
            const int row = idx >> 3;
            const int q   = idx & 7;
            const float* src = (row < MM)
                ? (W_lin + (size_t)row * DD + kt)
                : (W_t1 + (size_t)(row - MM) * DD + kt);
            const float4 wv = reinterpret_cast<const float4*>(src)[q];
            reinterpret_cast<float4*>(s_w + row * WSTR)[q] = wv;
        }
        __syncthreads();

        #pragma unroll
        for (int k8 = 0; k8 < 4; k8++) {
            const int ko = kt + k8 * 8;

            // A fragments (2 x m16k8), split hi/lo
            uint32_t ahi[2][4], alo[2][4];
            #pragma unroll
            for (int i = 0; i < 2; i++) {
                const float* ap = a_base + i * 16 * NXSTR + ko;
                split_tf32(ap[0],             ahi[i][0], alo[i][0]);  // (grp,   tig)
                split_tf32(ap[8 * NXSTR],     ahi[i][1], alo[i][1]);  // (grp+8, tig)
                split_tf32(ap[4],             ahi[i][2], alo[i][2]);  // (grp,   tig+4)
                split_tf32(ap[8 * NXSTR + 4], ahi[i][3], alo[i][3]);  // (grp+8, tig+4)
            }
            // B fragments (5 x k8n8), split hi/lo
            uint32_t bhi[5][2], blo[5][2];
            #pragma unroll
            for (int j = 0; j < 5; j++) {
                const float* bp = b_base + j * 8 * WSTR + (k8 * 8);
                split_tf32(bp[0], bhi[j][0], blo[j][0]);   // (k=tig,   n=grp)
                split_tf32(bp[4], bhi[j][1], blo[j][1]);   // (k=tig+4, n=grp)
            }
            #pragma unroll
            for (int i = 0; i < 2; i++) {
                #pragma unroll
                for (int j = 0; j < 5; j++) {
                    mma_tf32(acc[i][j], ahi[i], bhi[j]);
                    mma_tf32(acc[i][j], alo[i], bhi[j]);
                    mma_tf32(acc[i][j], ahi[i], blo[j]);
                }
            }
        }
    }

    // write logits (+ b_lin for mode cols) to smem
    #pragma unroll
    for (int i = 0; i < 2; i++) {
        #pragma unroll
        for (int j = 0; j < 5; j++) {
            const int r0 = wRow * 32 + i * 16 + grp;
            const int c0 = wCol * 40 + j * 8 + 2 * tig;
            s_log[r0 * LSTR + c0]           = acc[i][j][0] + (c0     < MM ? s_bl[c0]     : 0.f);
            s_log[r0 * LSTR + c0 + 1]       = acc[i][j][1] + (c0 + 1 < MM ? s_bl[c0 + 1] : 0.f);
            s_log[(r0 + 8) * LSTR + c0]     = acc[i][j][2] + (c0     < MM ? s_bl[c0]     : 0.f);
            s_log[(r0 + 8) * LSTR + c0 + 1] = acc[i][j][3] + (c0 + 1 < MM ? s_bl[c0 + 1] : 0.f);
        }
    }
    __syncthreads();

    // ---------------- Phase C/D: temperature + softmax (warp per row) ----
    float4 ps4 = make_float4(0.f, 0.f, 0.f, 0.f);
    for (int r = warp; r < TILE_N; r += 8) {
        float* lr = s_log + r * LSTR;

        // per-point temperature: GELU(exact) -> dot W_t2 -> softplus -> clamp
        const float tval = lr[MM + lane];
        const float gl = 0.5f * tval * (1.0f + erff(tval * 0.7071067811865476f));
        float cacc = gl * s_w2[lane];
        #pragma unroll
        for (int o = 16; o > 0; o >>= 1)
            cacc += __shfl_xor_sync(0xffffffffu, cacc, o);
        const float z   = cacc + bt2;
        const float sp  = (z > 20.f) ? z : log1pf(expf(z));
        const float tau = fminf(fmaxf(sp, 0.01f), 3.0f);
        const float itau = 1.0f / tau;
        const float ms = mass[(size_t)b * NN + n0 + r];

        // softmax over 128 modes (4 per lane)
        float4 l4 = *reinterpret_cast<float4*>(lr + lane * 4);
        l4.x *= itau; l4.y *= itau; l4.z *= itau; l4.w *= itau;
        float mx = fmaxf(fmaxf(l4.x, l4.y), fmaxf(l4.z, l4.w));
        #pragma unroll
        for (int o = 16; o > 0; o >>= 1)
            mx = fmaxf(mx, __shfl_xor_sync(0xffffffffu, mx, o));
        float4 e;
        e.x = expf(l4.x - mx); e.y = expf(l4.y - mx);
        e.z = expf(l4.z - mx); e.w = expf(l4.w - mx);
        float ssum = e.x + e.y + e.z + e.w;
        #pragma unroll
        for (int o = 16; o > 0; o >>= 1)
            ssum += __shfl_xor_sync(0xffffffffu, ssum, o);
        const float inv = 1.0f / ssum;
        float4 p;
        p.x = e.x * inv; p.y = e.y * inv; p.z = e.z * inv; p.w = e.w * inv;

        // trial_func: (B,N,M) coalesced float4 write
        *reinterpret_cast<float4*>(out + ((size_t)b * NN + n0 + r) * MM + lane * 4) = p;

        // trial_in_t values -> back into smem for transpose + partial sums
        float4 pm;
        pm.x = p.x * ms; pm.y = p.y * ms; pm.z = p.z * ms; pm.w = p.w * ms;
        *reinterpret_cast<float4*>(lr + lane * 4) = pm;
        ps4.x += pm.x; ps4.y += pm.y; ps4.z += pm.z; ps4.w += pm.w;
    }

    // deterministic per-warp partial sums (fixed-order combine)
    s_ps[warp * MM + lane * 4 + 0] = ps4.x;
    s_ps[warp * MM + lane * 4 + 1] = ps4.y;
    s_ps[warp * MM + lane * 4 + 2] = ps4.z;
    s_ps[warp * MM + lane * 4 + 3] = ps4.w;
    __syncthreads();

    if (tid < MM) {
        float t = 0.f;
        #pragma unroll
        for (int w = 0; w < 8; w++) t += s_ps[w * MM + tid];
        g_partials[((size_t)b * MM + tid) * CHUNKS + chunk] = t;
    }

    // ---------------- Phase E: transposed coalesced write of trial_in_t --
    const size_t off1 = (size_t)BB * NN * MM;
    #pragma unroll
    for (int it = 0; it < (TILE_N * MM) / 256; it++) {
        const int idx = it * 256 + tid;
        const int m  = idx >> 6;
        const int nl = idx & 63;
        out[off1 + ((size_t)b * MM + m) * NN + n0 + nl] = s_log[nl * LSTR + m];
    }
}

__global__ void norm_kernel(float* __restrict__ out)
{
    __shared__ float red[256];
    const int idx = blockIdx.x;   // b*M + m
    const int tid = threadIdx.x;
    const float* p = g_partials + (size_t)idx * CHUNKS;
    float s = 0.f;
    for (int k = tid; k < CHUNKS; k += 256) s += p[k];
    red[tid] = s;
    __syncthreads();
    for (int o = 128; o > 0; o >>= 1) {
        if (tid < o) red[tid] += red[tid + o];
        __syncthreads();
    }
    if (tid == 0)
        out[(size_t)2 * BB * NN * MM + idx] = 1.0f / (red[0] + 1e-6f);
}

extern "C" void kernel_launch(void* const* d_in, const int* in_sizes, int n_in,
                              void* d_out, int out_size)
{
    const float* x     = (const float*)d_in[0];
    const float* mass  = (const float*)d_in[1];
    const float* ln_g  = (const float*)d_in[2];
    const float* ln_b  = (const float*)d_in[3];
    const float* W_lin = (const float*)d_in[4];
    const float* b_lin = (const float*)d_in[5];
    const float* W_t1  = (const float*)d_in[6];
    const float* W_t2  = (const float*)d_in[7];
    const float* b_t2  = (const float*)d_in[8];
    float* out = (float*)d_out;

    const int smem_bytes =
        (TILE_N * NXSTR + NC * WSTR + TILE_N * LSTR + DD + DD + MM + HH + 8 * MM) * 4;

    cudaFuncSetAttribute(fused_kernel,
                         cudaFuncAttributeMaxDynamicSharedMemorySize, smem_bytes);

    fused_kernel<<<BB * CHUNKS, 256, smem_bytes>>>(
        x, mass, ln_g, ln_b, W_lin, b_lin, W_t1, W_t2, b_t2, out);
    norm_kernel<<<BB * MM, 256>>>(out);
}

// round 3
// speedup vs baseline: 1.7989x; 1.5426x over previous
#include <cuda_runtime.h>
#include <cuda_bf16.h>
#include <math.h>
#include <stdint.h>
#include <string.h>

#define BB 2
#define NN 65536
#define DD 512
#define MM 128
#define HH 32
#define TILE_N 64
#define CHUNKS (NN / TILE_N)   /* 1024 */
#define NC (MM + HH)           /* 160  */
#define NXW 260                /* u32 words per s_nx row (256 + 4 pad) */
#define WW  20                 /* u32 words per s_w chunk row (16 + 4 pad) */
#define LSTR 164               /* logits smem row stride (160 + 4 pad) */
#define NTHREADS 512

// Deterministic scratch (no device-side allocation).
__device__ float    g_partials[BB * MM * CHUNKS];
__device__ uint32_t g_w_hi[NC * 256];   // packed bf16x2, [row][k/2]
__device__ uint32_t g_w_lo[NC * 256];

__device__ __forceinline__ uint32_t packbf(float a, float b)
{
    __nv_bfloat162 t;
    t.x = __float2bfloat16(a);
    t.y = __float2bfloat16(b);
    uint32_t r;
    memcpy(&r, &t, 4);
    return r;
}

__device__ __forceinline__ void mma_bf16(float* c, const uint32_t* a, const uint32_t* b)
{
    asm volatile(
        "mma.sync.aligned.m16n8k16.row.col.f32.bf16.bf16.f32 "
        "{%0,%1,%2,%3}, {%4,%5,%6,%7}, {%8,%9}, {%0,%1,%2,%3};"
        : "+f"(c[0]), "+f"(c[1]), "+f"(c[2]), "+f"(c[3])
        : "r"(a[0]), "r"(a[1]), "r"(a[2]), "r"(a[3]), "r"(b[0]), "r"(b[1]));
}

// One-time (per launch) W split: fp32 -> bf16 hi/lo packed pairs.
__global__ void prep_w(const float* __restrict__ W_lin, const float* __restrict__ W_t1)
{
    const int idx = blockIdx.x * 256 + threadIdx.x;   // 0 .. 160*256-1
    if (idx >= NC * 256) return;
    const int row = idx >> 8;
    const int w   = idx & 255;
    const float* src = (row < MM) ? (W_lin + (size_t)row * DD)
                                  : (W_t1 + (size_t)(row - MM) * DD);
    const float x0 = src[2 * w], x1 = src[2 * w + 1];
    const __nv_bfloat16 h0 = __float2bfloat16(x0);
    const __nv_bfloat16 h1 = __float2bfloat16(x1);
    const float l0 = x0 - __bfloat162float(h0);
    const float l1 = x1 - __bfloat162float(h1);
    g_w_hi[idx] = packbf(x0, x1);
    g_w_lo[idx] = packbf(l0, l1);
}

__global__ void __launch_bounds__(NTHREADS, 1)
fused_kernel(const float* __restrict__ x, const float* __restrict__ mass,
             const float* __restrict__ ln_g, const float* __restrict__ ln_b,
             const float* __restrict__ b_lin, const float* __restrict__ W_t2,
             const float* __restrict__ b_t2, float* __restrict__ out)
{
    extern __shared__ uint32_t smu[];
    uint32_t* s_nxh = smu;                  // 64*260 = 16640
    uint32_t* s_nxl = smu + 16640;          // 16640
    uint32_t* s_wh  = smu + 33280;          // 160*20 = 3200
    uint32_t* s_wl  = smu + 36480;          // 3200
    float*    s_g   = (float*)(smu + 39680);// 512
    float*    s_b   = s_g + DD;             // 512
    float*    s_bl  = s_b + DD;             // 128
    float*    s_w2  = s_bl + MM;            // 32
    float*    s_ps  = s_w2 + HH;            // 16*128 = 2048
    float*    s_log = (float*)smu;          // aliases s_nx (64*164 <= 16640)

    const int tid   = threadIdx.x;
    const int lane  = tid & 31;
    const int warp  = tid >> 5;
    const int b     = blockIdx.x / CHUNKS;
    const int chunk = blockIdx.x % CHUNKS;
    const int n0    = chunk * TILE_N;

    for (int i = tid; i < DD; i += NTHREADS) { s_g[i] = ln_g[i]; s_b[i] = ln_b[i]; }
    if (tid < MM) s_bl[tid] = b_lin[tid];
    if (tid < HH) s_w2[tid] = W_t2[tid];
    const float bt2 = b_t2[0];

    __syncthreads();

    // ---------------- Phase A: LayerNorm -> packed bf16 hi/lo ----------------
    for (int r = warp; r < TILE_N; r += 16) {
        const float4* xr = reinterpret_cast<const float4*>(
            x + ((size_t)(b * NN + n0 + r)) * DD);
        float4 v[4];
        float s = 0.f, sq = 0.f;
        #pragma unroll
        for (int q = 0; q < 4; q++) {
            v[q] = xr[lane + 32 * q];
            s  += v[q].x + v[q].y + v[q].z + v[q].w;
            sq += v[q].x * v[q].x + v[q].y * v[q].y + v[q].z * v[q].z + v[q].w * v[q].w;
        }
        #pragma unroll
        for (int o = 16; o > 0; o >>= 1) {
            s  += __shfl_xor_sync(0xffffffffu, s,  o);
            sq += __shfl_xor_sync(0xffffffffu, sq, o);
        }
        const float mu   = s * (1.0f / DD);
        const float var  = sq * (1.0f / DD) - mu * mu;
        const float rstd = rsqrtf(var + 1e-5f);
        #pragma unroll
        for (int q = 0; q < 4; q++) {
            const int k = (lane + 32 * q) * 4;
            float4 o4;
            o4.x = (v[q].x - mu) * rstd * s_g[k + 0] + s_b[k + 0];
            o4.y = (v[q].y - mu) * rstd * s_g[k + 1] + s_b[k + 1];
            o4.z = (v[q].z - mu) * rstd * s_g[k + 2] + s_b[k + 2];
            o4.w = (v[q].w - mu) * rstd * s_g[k + 3] + s_b[k + 3];
            const float hx = __bfloat162float(__float2bfloat16(o4.x));
            const float hy = __bfloat162float(__float2bfloat16(o4.y));
            const float hz = __bfloat162float(__float2bfloat16(o4.z));
            const float hw = __bfloat162float(__float2bfloat16(o4.w));
            uint2 hv, lv;
            hv.x = packbf(o4.x, o4.y); hv.y = packbf(o4.z, o4.w);
            lv.x = packbf(o4.x - hx, o4.y - hy); lv.y = packbf(o4.z - hz, o4.w - hw);
            const int wofs = r * NXW + (lane + 32 * q) * 2;
            *reinterpret_cast<uint2*>(s_nxh + wofs) = hv;
            *reinterpret_cast<uint2*>(s_nxl + wofs) = lv;
        }
    }

    // ------------ Phase B: GEMM via mma.sync bf16 m16n8k16, 3-term split ------
    // 16 warps as 4x4 grid; warp tile 16 rows x 40 cols.
    const int wRow = warp >> 2;           // 0..3 -> rows wRow*16 + [0,16)
    const int wCol = warp & 3;            // 0..3 -> cols wCol*40 + [0,40)
    const int grp  = lane >> 2;           // 0..7
    const int tig  = lane & 3;            // 0..3

    float acc[5][4];
    #pragma unroll
    for (int j = 0; j < 5; j++)
        #pragma unroll
        for (int q = 0; q < 4; q++) acc[j][q] = 0.f;

    // W chunk register-prefetch mapping: 1280 uint4 per chunk (hi then lo).
    int pf_row[3], pf_q[3], pf_arr[3], pf_valid[3];
    #pragma unroll
    for (int s2 = 0; s2 < 3; s2++) {
        const int idx = tid + s2 * NTHREADS;
        pf_valid[s2] = (idx < 1280);
        const int r2 = idx % 640;
        pf_arr[s2] = (idx >= 640);
        pf_row[s2] = r2 >> 2;
        pf_q[s2]   = r2 & 3;
    }
    uint4 wbuf[3];
    #pragma unroll
    for (int s2 = 0; s2 < 3; s2++) {
        if (pf_valid[s2]) {
            const uint32_t* gp = (pf_arr[s2] ? g_w_lo : g_w_hi)
                               + pf_row[s2] * 256 + pf_q[s2] * 4;   // kc = 0
            wbuf[s2] = *reinterpret_cast<const uint4*>(gp);
        }
    }

    const int arow = wRow * 16 + grp;
    const uint32_t* ah_base = s_nxh + arow * NXW + tig;
    const uint32_t* al_base = s_nxl + arow * NXW + tig;

    for (int kc = 0; kc < 16; kc++) {
        __syncthreads();   // prev chunk consumed / s_nx ready (first iter)
        #pragma unroll
        for (int s2 = 0; s2 < 3; s2++) {
            if (pf_valid[s2]) {
                uint32_t* sp = (pf_arr[s2] ? s_wl : s_wh)
                             + pf_row[s2] * WW + pf_q[s2] * 4;
                *reinterpret_cast<uint4*>(sp) = wbuf[s2];
            }
        }
        __syncthreads();
        if (kc < 15) {
            #pragma unroll
            for (int s2 = 0; s2 < 3; s2++) {
                if (pf_valid[s2]) {
                    const uint32_t* gp = (pf_arr[s2] ? g_w_lo : g_w_hi)
                                       + pf_row[s2] * 256 + (kc + 1) * 16 + pf_q[s2] * 4;
                    wbuf[s2] = *reinterpret_cast<const uint4*>(gp);
                }
            }
        }
        #pragma unroll
        for (int ks = 0; ks < 2; ks++) {
            const int ko = kc * 16 + ks * 8;
            uint32_t ah[4], al[4];
            const uint32_t* aph = ah_base + ko;
            const uint32_t* apl = al_base + ko;
            ah[0] = aph[0]; ah[1] = aph[8 * NXW]; ah[2] = aph[4]; ah[3] = aph[8 * NXW + 4];
            al[0] = apl[0]; al[1] = apl[8 * NXW]; al[2] = apl[4]; al[3] = apl[8 * NXW + 4];
            #pragma unroll
            for (int j = 0; j < 5; j++) {
                const int brow = (wCol * 40 + j * 8 + grp) * WW + ks * 8 + tig;
                uint32_t bh[2], bl[2];
                bh[0] = s_wh[brow];     bh[1] = s_wh[brow + 4];
                bl[0] = s_wl[brow];     bl[1] = s_wl[brow + 4];
                mma_bf16(acc[j], ah, bh);
                mma_bf16(acc[j], al, bh);
                mma_bf16(acc[j], ah, bl);
            }
        }
    }

    __syncthreads();   // all warps done reading s_nx before s_log overwrite

    // write logits (+ b_lin for mode cols) to smem
    #pragma unroll
    for (int j = 0; j < 5; j++) {
        const int r0 = wRow * 16 + grp;
        const int c0 = wCol * 40 + j * 8 + 2 * tig;
        const float bb0 = (c0     < MM) ? s_bl[c0]     : 0.f;
        const float bb1 = (c0 + 1 < MM) ? s_bl[c0 + 1] : 0.f;
        s_log[r0 * LSTR + c0]           = acc[j][0] + bb0;
        s_log[r0 * LSTR + c0 + 1]       = acc[j][1] + bb1;
        s_log[(r0 + 8) * LSTR + c0]     = acc[j][2] + bb0;
        s_log[(r0 + 8) * LSTR + c0 + 1] = acc[j][3] + bb1;
    }
    __syncthreads();

    // ---------------- Phase C/D: temperature + softmax (warp per row) ----
    float4 ps4 = make_float4(0.f, 0.f, 0.f, 0.f);
    for (int r = warp; r < TILE_N; r += 16) {
        float* lr = s_log + r * LSTR;

        const float tval = lr[MM + lane];
        const float gl = 0.5f * tval * (1.0f + erff(tval * 0.7071067811865476f));
        float cacc = gl * s_w2[lane];
        #pragma unroll
        for (int o = 16; o > 0; o >>= 1)
            cacc += __shfl_xor_sync(0xffffffffu, cacc, o);
        const float z   = cacc + bt2;
        const float sp  = (z > 20.f) ? z : log1pf(expf(z));
        const float tau = fminf(fmaxf(sp, 0.01f), 3.0f);
        const float itau = 1.0f / tau;
        const float ms = mass[(size_t)b * NN + n0 + r];

        float4 l4 = *reinterpret_cast<float4*>(lr + lane * 4);
        l4.x *= itau; l4.y *= itau; l4.z *= itau; l4.w *= itau;
        float mx = fmaxf(fmaxf(l4.x, l4.y), fmaxf(l4.z, l4.w));
        #pragma unroll
        for (int o = 16; o > 0; o >>= 1)
            mx = fmaxf(mx, __shfl_xor_sync(0xffffffffu, mx, o));
        float4 e;
        e.x = expf(l4.x - mx); e.y = expf(l4.y - mx);
        e.z = expf(l4.z - mx); e.w = expf(l4.w - mx);
        float ssum = e.x + e.y + e.z + e.w;
        #pragma unroll
        for (int o = 16; o > 0; o >>= 1)
            ssum += __shfl_xor_sync(0xffffffffu, ssum, o);
        const float inv = 1.0f / ssum;
        float4 p;
        p.x = e.x * inv; p.y = e.y * inv; p.z = e.z * inv; p.w = e.w * inv;

        *reinterpret_cast<float4*>(out + ((size_t)b * NN + n0 + r) * MM + lane * 4) = p;

        float4 pm;
        pm.x = p.x * ms; pm.y = p.y * ms; pm.z = p.z * ms; pm.w = p.w * ms;
        *reinterpret_cast<float4*>(lr + lane * 4) = pm;
        ps4.x += pm.x; ps4.y += pm.y; ps4.z += pm.z; ps4.w += pm.w;
    }

    s_ps[warp * MM + lane * 4 + 0] = ps4.x;
    s_ps[warp * MM + lane * 4 + 1] = ps4.y;
    s_ps[warp * MM + lane * 4 + 2] = ps4.z;
    s_ps[warp * MM + lane * 4 + 3] = ps4.w;
    __syncthreads();

    if (tid < MM) {
        float t = 0.f;
        #pragma unroll
        for (int w = 0; w < 16; w++) t += s_ps[w * MM + tid];
        g_partials[((size_t)b * MM + tid) * CHUNKS + chunk] = t;
    }

    // ---------------- Phase E: transposed coalesced write of trial_in_t --
    const size_t off1 = (size_t)BB * NN * MM;
    #pragma unroll
    for (int it = 0; it < (TILE_N * MM) / NTHREADS; it++) {
        const int idx = it * NTHREADS + tid;
        const int m  = idx >> 6;
        const int nl = idx & 63;
        out[off1 + ((size_t)b * MM + m) * NN + n0 + nl] = s_log[nl * LSTR + m];
    }
}

__global__ void norm_kernel(float* __restrict__ out)
{
    __shared__ float red[256];
    const int idx = blockIdx.x;   // b*M + m
    const int tid = threadIdx.x;
    const float* p = g_partials + (size_t)idx * CHUNKS;
    float s = 0.f;
    for (int k = tid; k < CHUNKS; k += 256) s += p[k];
    red[tid] = s;
    __syncthreads();
    for (int o = 128; o > 0; o >>= 1) {
        if (tid < o) red[tid] += red[tid + o];
        __syncthreads();
    }
    if (tid == 0)
        out[(size_t)2 * BB * NN * MM + idx] = 1.0f / (red[0] + 1e-6f);
}

extern "C" void kernel_launch(void* const* d_in, const int* in_sizes, int n_in,
                              void* d_out, int out_size)
{
    const float* x     = (const float*)d_in[0];
    const float* mass  = (const float*)d_in[1];
    const float* ln_g  = (const float*)d_in[2];
    const float* ln_b  = (const float*)d_in[3];
    const float* W_lin = (const float*)d_in[4];
    const float* b_lin = (const float*)d_in[5];
    const float* W_t1  = (const float*)d_in[6];
    const float* W_t2  = (const float*)d_in[7];
    const float* b_t2  = (const float*)d_in[8];
    float* out = (float*)d_out;

    prep_w<<<NC, 256>>>(W_lin, W_t1);

    const int smem_bytes = (39680 + 512 + 512 + 128 + 32 + 16 * 128) * 4;  // ~171.6 KB
    cudaFuncSetAttribute(fused_kernel,
                         cudaFuncAttributeMaxDynamicSharedMemorySize, smem_bytes);

    fused_kernel<<<BB * CHUNKS, NTHREADS, smem_bytes>>>(
        x, mass, ln_g, ln_b, b_lin, W_t2, b_t2, out);
    norm_kernel<<<BB * MM, 256>>>(out);
}

// round 5
// speedup vs baseline: 1.9541x; 1.0863x over previous
#include <cuda_runtime.h>
#include <cuda_bf16.h>
#include <math.h>
#include <stdint.h>
#include <string.h>

#define BB 2
#define NN 65536
#define DD 512
#define MM 128
#define HH 32
#define TILE_N 64
#define CHUNKS (NN / TILE_N)   /* 1024 */
#define NC (MM + HH)           /* 160  */
#define NXW 260                /* u32 words per s_nx row (256 + 4 pad) */
#define WW  20                 /* u32 words per s_w chunk row (16 + 4 pad) */
#define LSTR 164               /* logits smem row stride (160 + 4 pad) */
#define NTHREADS 512

/* Deterministic scratch (no device-side allocation). */
__device__ float    g_partials[BB * MM * CHUNKS];
__device__ uint32_t g_w_hi[NC * 256];   /* packed bf16x2, [row][k/2] */
__device__ uint32_t g_w_lo[NC * 256];

__device__ __forceinline__ uint32_t smem_u32(const void* p)
{
    uint32_t a;
    asm("{ .reg .u64 t; cvta.to.shared.u64 t, %1; cvt.u32.u64 %0, t; }"
        : "=r"(a) : "l"(p));
    return a;
}

__device__ __forceinline__ uint32_t packbf(float a, float b)
{
    __nv_bfloat162 t;
    t.x = __float2bfloat16(a);
    t.y = __float2bfloat16(b);
    uint32_t r;
    memcpy(&r, &t, 4);
    return r;
}

__device__ __forceinline__ void mma_bf16(float* c, const uint32_t* a, const uint32_t* b)
{
    asm volatile(
        "mma.sync.aligned.m16n8k16.row.col.f32.bf16.bf16.f32 "
        "{%0,%1,%2,%3}, {%4,%5,%6,%7}, {%8,%9}, {%0,%1,%2,%3};"
        : "+f"(c[0]), "+f"(c[1]), "+f"(c[2]), "+f"(c[3])
        : "r"(a[0]), "r"(a[1]), "r"(a[2]), "r"(a[3]), "r"(b[0]), "r"(b[1]));
}

__device__ __forceinline__ void cp16(uint32_t dst, const uint32_t* src)
{
    asm volatile("cp.async.cg.shared.global [%0], [%1], 16;"
                 :: "r"(dst), "l"(__cvta_generic_to_global(src)) : "memory");
}
#define CP_COMMIT() asm volatile("cp.async.commit_group;" ::: "memory")
#define CP_WAIT0()  asm volatile("cp.async.wait_group 0;" ::: "memory")

/* One-time W split: fp32 -> bf16 hi/lo packed pairs. */
__global__ void prep_w(const float* __restrict__ W_lin, const float* __restrict__ W_t1)
{
    const int idx = blockIdx.x * 256 + threadIdx.x;   /* 0 .. 160*256-1 */
    if (idx >= NC * 256) return;
    const int row = idx >> 8;
    const int w   = idx & 255;
    const float* src = (row < MM) ? (W_lin + (size_t)row * DD)
                                  : (W_t1 + (size_t)(row - MM) * DD);
    const float x0 = src[2 * w], x1 = src[2 * w + 1];
    const float h0 = __bfloat162float(__float2bfloat16(x0));
    const float h1 = __bfloat162float(__float2bfloat16(x1));
    g_w_hi[idx] = packbf(x0, x1);
    g_w_lo[idx] = packbf(x0 - h0, x1 - h1);
}

/* Issue async copy of W chunk kc into buffer buf (1280 x 16B: hi 640, lo 640). */
__device__ __forceinline__ void load_chunk_async(uint32_t wbase_u32, int kc, int buf, int tid)
{
    const uint32_t dbase = wbase_u32 + buf * (2 * NC * WW * 4);
    #pragma unroll
    for (int s = 0; s < 3; s++) {
        const int idx = tid + s * NTHREADS;
        if (idx < 1280) {
            const int arr = (idx >= 640);
            const int r2  = arr ? (idx - 640) : idx;
            const int row = r2 >> 2;
            const int q   = r2 & 3;
            const uint32_t* src = (arr ? g_w_lo : g_w_hi) + row * 256 + kc * 16 + q * 4;
            const uint32_t dst = dbase + (arr * NC * WW + row * WW + q * 4) * 4;
            cp16(dst, src);
        }
    }
    CP_COMMIT();
}

__global__ void __launch_bounds__(NTHREADS, 1)
fused_kernel(const float* __restrict__ x, const float* __restrict__ mass,
             const float* __restrict__ ln_g, const float* __restrict__ ln_b,
             const float* __restrict__ b_lin, const float* __restrict__ W_t2,
             const float* __restrict__ b_t2, float* __restrict__ out)
{
    extern __shared__ uint32_t smu[];
    uint32_t* s_nxh = smu;                  /* 64*260 = 16640 */
    uint32_t* s_nxl = smu + 16640;          /* 16640 */
    uint32_t* s_wb  = smu + 33280;          /* 2 bufs x (hi 160*20 + lo 160*20) = 12800 */
    float*    s_g   = (float*)(smu + 46080);/* 512 */
    float*    s_b   = s_g + DD;             /* 512 */
    float*    s_bl  = s_b + DD;             /* 128 */
    float*    s_w2  = s_bl + MM;            /* 32  */
    float*    s_ps  = s_w2 + HH;            /* 16*128 = 2048 */
    float*    s_log = (float*)smu;          /* aliases s_nx after GEMM */

    const uint32_t wbase_u32 = smem_u32(s_wb);

    const int tid   = threadIdx.x;
    const int lane  = tid & 31;
    const int warp  = tid >> 5;
    const int b     = blockIdx.x / CHUNKS;
    const int chunk = blockIdx.x % CHUNKS;
    const int n0    = chunk * TILE_N;

    /* kick off W chunk 0 immediately — hides under x loads in LN */
    load_chunk_async(wbase_u32, 0, 0, tid);

    for (int i = tid; i < DD; i += NTHREADS) { s_g[i] = ln_g[i]; s_b[i] = ln_b[i]; }
    if (tid < MM) s_bl[tid] = b_lin[tid];
    if (tid < HH) s_w2[tid] = W_t2[tid];
    const float bt2 = b_t2[0];

    __syncthreads();

    /* ---------------- Phase A: LayerNorm -> packed bf16 hi/lo ---------------- */
    for (int r = warp; r < TILE_N; r += 16) {
        const float4* xr = reinterpret_cast<const float4*>(
            x + ((size_t)(b * NN + n0 + r)) * DD);
        float4 v[4];
        float s = 0.f, sq = 0.f;
        #pragma unroll
        for (int q = 0; q < 4; q++) {
            v[q] = xr[lane + 32 * q];
            s  += v[q].x + v[q].y + v[q].z + v[q].w;
            sq += v[q].x * v[q].x + v[q].y * v[q].y + v[q].z * v[q].z + v[q].w * v[q].w;
        }
        #pragma unroll
        for (int o = 16; o > 0; o >>= 1) {
            s  += __shfl_xor_sync(0xffffffffu, s,  o);
            sq += __shfl_xor_sync(0xffffffffu, sq, o);
        }
        const float mu   = s * (1.0f / DD);
        const float var  = sq * (1.0f / DD) - mu * mu;
        const float rstd = rsqrtf(var + 1e-5f);
        #pragma unroll
        for (int q = 0; q < 4; q++) {
            const int k = (lane + 32 * q) * 4;
            float4 o4;
            o4.x = (v[q].x - mu) * rstd * s_g[k + 0] + s_b[k + 0];
            o4.y = (v[q].y - mu) * rstd * s_g[k + 1] + s_b[k + 1];
            o4.z = (v[q].z - mu) * rstd * s_g[k + 2] + s_b[k + 2];
            o4.w = (v[q].w - mu) * rstd * s_g[k + 3] + s_b[k + 3];
            const float hx = __bfloat162float(__float2bfloat16(o4.x));
            const float hy = __bfloat162float(__float2bfloat16(o4.y));
            const float hz = __bfloat162float(__float2bfloat16(o4.z));
            const float hw = __bfloat162float(__float2bfloat16(o4.w));
            uint2 hv, lv;
            hv.x = packbf(o4.x, o4.y); hv.y = packbf(o4.z, o4.w);
            lv.x = packbf(o4.x - hx, o4.y - hy); lv.y = packbf(o4.z - hz, o4.w - hw);
            const int wofs = r * NXW + (lane + 32 * q) * 2;
            *reinterpret_cast<uint2*>(s_nxh + wofs) = hv;
            *reinterpret_cast<uint2*>(s_nxl + wofs) = lv;
        }
    }

    /* ------------ Phase B: bf16 m16n8k16 GEMM, 3-term split, pipelined ------- */
    const int wRow = warp >> 2;           /* 0..3 -> rows wRow*16 + [0,16) */
    const int wCol = warp & 3;            /* 0..3 -> cols wCol*40 + [0,40) */
    const int grp  = lane >> 2;           /* 0..7 */
    const int tig  = lane & 3;            /* 0..3 */

    float acc[5][4];
    #pragma unroll
    for (int j = 0; j < 5; j++)
        #pragma unroll
        for (int q = 0; q < 4; q++) acc[j][q] = 0.f;

    const int arow = wRow * 16 + grp;
    const uint32_t* ah_base = s_nxh + arow * NXW + tig;
    const uint32_t* al_base = s_nxl + arow * NXW + tig;

    CP_WAIT0();          /* chunk 0 landed */
    __syncthreads();     /* s_nx ready + chunk 0 visible */

    for (int kc = 0; kc < 16; kc++) {
        if (kc < 15) load_chunk_async(wbase_u32, kc + 1, (kc + 1) & 1, tid);

        const uint32_t* bh_buf = s_wb + (kc & 1) * (2 * NC * WW);
        const uint32_t* bl_buf = bh_buf + NC * WW;

        #pragma unroll
        for (int ks = 0; ks < 2; ks++) {
            const int ko = kc * 16 + ks * 8;
            uint32_t ah[4], al[4];
            const uint32_t* aph = ah_base + ko;
            const uint32_t* apl = al_base + ko;
            ah[0] = aph[0]; ah[1] = aph[8 * NXW]; ah[2] = aph[4]; ah[3] = aph[8 * NXW + 4];
            al[0] = apl[0]; al[1] = apl[8 * NXW]; al[2] = apl[4]; al[3] = apl[8 * NXW + 4];
            #pragma unroll
            for (int j = 0; j < 5; j++) {
                const int brow = (wCol * 40 + j * 8 + grp) * WW + ks * 8 + tig;
                uint32_t bh[2], bl[2];
                bh[0] = bh_buf[brow]; bh[1] = bh_buf[brow + 4];
                bl[0] = bl_buf[brow]; bl[1] = bl_buf[brow + 4];
                mma_bf16(acc[j], ah, bh);
                mma_bf16(acc[j], al, bh);
                mma_bf16(acc[j], ah, bl);
            }
        }
        if (kc < 15) CP_WAIT0();
        __syncthreads();
    }

    /* write logits (+ b_lin for mode cols) to smem (aliases s_nx, synced above) */
    #pragma unroll
    for (int j = 0; j < 5; j++) {
        const int r0 = wRow * 16 + grp;
        const int c0 = wCol * 40 + j * 8 + 2 * tig;
        const float bb0 = (c0     < MM) ? s_bl[c0]     : 0.f;
        const float bb1 = (c0 + 1 < MM) ? s_bl[c0 + 1] : 0.f;
        s_log[r0 * LSTR + c0]           = acc[j][0] + bb0;
        s_log[r0 * LSTR + c0 + 1]       = acc[j][1] + bb1;
        s_log[(r0 + 8) * LSTR + c0]     = acc[j][2] + bb0;
        s_log[(r0 + 8) * LSTR + c0 + 1] = acc[j][3] + bb1;
    }
    __syncthreads();

    /* ---------------- Phase C/D: temperature + softmax (warp per row) ---- */
    float4 ps4 = make_float4(0.f, 0.f, 0.f, 0.f);
    for (int r = warp; r < TILE_N; r += 16) {
        float* lr = s_log + r * LSTR;

        const float tval = lr[MM + lane];
        const float gl = 0.5f * tval * (1.0f + erff(tval * 0.7071067811865476f));
        float cacc = gl * s_w2[lane];
        #pragma unroll
        for (int o = 16; o > 0; o >>= 1)
            cacc += __shfl_xor_sync(0xffffffffu, cacc, o);
        const float z   = cacc + bt2;
        const float sp  = (z > 20.f) ? z : log1pf(expf(z));
        const float tau = fminf(fmaxf(sp, 0.01f), 3.0f);
        const float itau = 1.0f / tau;
        const float ms = mass[(size_t)b * NN + n0 + r];

        float4 l4 = *reinterpret_cast<float4*>(lr + lane * 4);
        l4.x *= itau; l4.y *= itau; l4.z *= itau; l4.w *= itau;
        float mx = fmaxf(fmaxf(l4.x, l4.y), fmaxf(l4.z, l4.w));
        #pragma unroll
        for (int o = 16; o > 0; o >>= 1)
            mx = fmaxf(mx, __shfl_xor_sync(0xffffffffu, mx, o));
        float4 e;
        e.x = expf(l4.x - mx); e.y = expf(l4.y - mx);
        e.z = expf(l4.z - mx); e.w = expf(l4.w - mx);
        float ssum = e.x + e.y + e.z + e.w;
        #pragma unroll
        for (int o = 16; o > 0; o >>= 1)
            ssum += __shfl_xor_sync(0xffffffffu, ssum, o);
        const float inv = 1.0f / ssum;
        float4 p;
        p.x = e.x * inv; p.y = e.y * inv; p.z = e.z * inv; p.w = e.w * inv;

        *reinterpret_cast<float4*>(out + ((size_t)b * NN + n0 + r) * MM + lane * 4) = p;

        float4 pm;
        pm.x = p.x * ms; pm.y = p.y * ms; pm.z = p.z * ms; pm.w = p.w * ms;
        *reinterpret_cast<float4*>(lr + lane * 4) = pm;
        ps4.x += pm.x; ps4.y += pm.y; ps4.z += pm.z; ps4.w += pm.w;
    }

    s_ps[warp * MM + lane * 4 + 0] = ps4.x;
    s_ps[warp * MM + lane * 4 + 1] = ps4.y;
    s_ps[warp * MM + lane * 4 + 2] = ps4.z;
    s_ps[warp * MM + lane * 4 + 3] = ps4.w;
    __syncthreads();

    if (tid < MM) {
        float t = 0.f;
        #pragma unroll
        for (int w = 0; w < 16; w++) t += s_ps[w * MM + tid];
        g_partials[((size_t)b * MM + tid) * CHUNKS + chunk] = t;
    }

    /* ---------------- Phase E: transposed coalesced write of trial_in_t -- */
    const size_t off1 = (size_t)BB * NN * MM;
    #pragma unroll
    for (int it = 0; it < (TILE_N * MM) / NTHREADS; it++) {
        const int idx = it * NTHREADS + tid;
        const int m  = idx >> 6;
        const int nl = idx & 63;
        out[off1 + ((size_t)b * MM + m) * NN + n0 + nl] = s_log[nl * LSTR + m];
    }
}

__global__ void norm_kernel(float* __restrict__ out)
{
    __shared__ float red[256];
    const int idx = blockIdx.x;   /* b*M + m */
    const int tid = threadIdx.x;
    const float* p = g_partials + (size_t)idx * CHUNKS;
    float s = 0.f;
    for (int k = tid; k < CHUNKS; k += 256) s += p[k];
    red[tid] = s;
    __syncthreads();
    for (int o = 128; o > 0; o >>= 1) {
        if (tid < o) red[tid] += red[tid + o];
        __syncthreads();
    }
    if (tid == 0)
        out[(size_t)2 * BB * NN * MM + idx] = 1.0f / (red[0] + 1e-6f);
}

extern "C" void kernel_launch(void* const* d_in, const int* in_sizes, int n_in,
                              void* d_out, int out_size)
{
    const float* x     = (const float*)d_in[0];
    const float* mass  = (const float*)d_in[1];
    const float* ln_g  = (const float*)d_in[2];
    const float* ln_b  = (const float*)d_in[3];
    const float* W_lin = (const float*)d_in[4];
    const float* b_lin = (const float*)d_in[5];
    const float* W_t1  = (const float*)d_in[6];
    const float* W_t2  = (const float*)d_in[7];
    const float* b_t2  = (const float*)d_in[8];
    float* out = (float*)d_out;

    prep_w<<<NC, 256>>>(W_lin, W_t1);

    const int smem_bytes = (46080 + DD + DD + MM + HH + 16 * 128) * 4;  /* ~197 KB */
    cudaFuncSetAttribute(fused_kernel,
                         cudaFuncAttributeMaxDynamicSharedMemorySize, smem_bytes);

    fused_kernel<<<BB * CHUNKS, NTHREADS, smem_bytes>>>(
        x, mass, ln_g, ln_b, b_lin, W_t2, b_t2, out);
    norm_kernel<<<BB * MM, 256>>>(out);
}

// round 6
// speedup vs baseline: 2.6909x; 1.3770x over previous
#include <cuda_runtime.h>
#include <cuda_fp16.h>
#include <math.h>
#include <stdint.h>
#include <string.h>

#define BB 2
#define NN 65536
#define DD 512
#define MM 128
#define HH 32
#define TILE_N 32
#define CHUNKS (NN / TILE_N)   /* 2048 */
#define NC (MM + HH)           /* 160  */
#define NXW 260                /* u32 words per s_nx row (256 + 4 pad) */
#define WW  20                 /* u32 words per s_w chunk row (16 + 4 pad) */
#define LSTR 164               /* logits smem row stride (160 + 4 pad) */
#define NTHREADS 256

/* Deterministic scratch (no device-side allocation). */
__device__ float    g_partials[BB * MM * CHUNKS];
__device__ uint32_t g_w[NC * 256];   /* packed fp16x2 (hi only), [row][k/2] */

__device__ __forceinline__ uint32_t smem_u32(const void* p)
{
    uint32_t a;
    asm("{ .reg .u64 t; cvta.to.shared.u64 t, %1; cvt.u32.u64 %0, t; }"
        : "=r"(a) : "l"(p));
    return a;
}

__device__ __forceinline__ uint32_t packh(float a, float b)
{
    __half2 t;
    t.x = __float2half_rn(a);
    t.y = __float2half_rn(b);
    uint32_t r;
    memcpy(&r, &t, 4);
    return r;
}

__device__ __forceinline__ void mma_f16(float* c, const uint32_t* a, const uint32_t* b)
{
    asm volatile(
        "mma.sync.aligned.m16n8k16.row.col.f32.f16.f16.f32 "
        "{%0,%1,%2,%3}, {%4,%5,%6,%7}, {%8,%9}, {%0,%1,%2,%3};"
        : "+f"(c[0]), "+f"(c[1]), "+f"(c[2]), "+f"(c[3])
        : "r"(a[0]), "r"(a[1]), "r"(a[2]), "r"(a[3]), "r"(b[0]), "r"(b[1]));
}

__device__ __forceinline__ void cp16(uint32_t dst, const uint32_t* src)
{
    asm volatile("cp.async.cg.shared.global [%0], [%1], 16;"
                 :: "r"(dst), "l"(__cvta_generic_to_global(src)) : "memory");
}
#define CP_COMMIT() asm volatile("cp.async.commit_group;" ::: "memory")
#define CP_WAIT0()  asm volatile("cp.async.wait_group 0;" ::: "memory")

/* One-time W convert: fp32 -> fp16 packed pairs (hi only). */
__global__ void prep_w(const float* __restrict__ W_lin, const float* __restrict__ W_t1)
{
    const int idx = blockIdx.x * 256 + threadIdx.x;   /* 0 .. 160*256-1 */
    if (idx >= NC * 256) return;
    const int row = idx >> 8;
    const int w   = idx & 255;
    const float* src = (row < MM) ? (W_lin + (size_t)row * DD)
                                  : (W_t1 + (size_t)(row - MM) * DD);
    g_w[idx] = packh(src[2 * w], src[2 * w + 1]);
}

/* Async copy of W chunk kc (640 x 16B) into buffer buf. */
__device__ __forceinline__ void load_chunk_async(uint32_t wbase_u32, int kc, int buf, int tid)
{
    const uint32_t dbase = wbase_u32 + buf * (NC * WW * 4);
    #pragma unroll
    for (int s = 0; s < 3; s++) {
        const int idx = tid + s * NTHREADS;
        if (idx < 640) {
            const int row = idx >> 2;
            const int q   = idx & 3;
            cp16(dbase + (row * WW + q * 4) * 4, g_w + row * 256 + kc * 16 + q * 4);
        }
    }
    CP_COMMIT();
}

__global__ void __launch_bounds__(NTHREADS, 2)
fused_kernel(const float* __restrict__ x, const float* __restrict__ mass,
             const float* __restrict__ ln_g, const float* __restrict__ ln_b,
             const float* __restrict__ b_lin, const float* __restrict__ W_t2,
             const float* __restrict__ b_t2, float* __restrict__ out)
{
    extern __shared__ uint32_t smu[];
    uint32_t* s_nxh = smu;                   /* 32*260 = 8320 */
    uint32_t* s_nxl = smu + 8320;            /* 8320 */
    uint32_t* s_wb  = smu + 16640;           /* 2 bufs x 160*20 = 6400 */
    float*    s_g   = (float*)(smu + 23040); /* 512 */
    float*    s_b   = s_g + DD;              /* 512 */
    float*    s_bl  = s_b + DD;              /* 128 */
    float*    s_w2  = s_bl + MM;             /* 32  */
    float*    s_ps  = s_w2 + HH;             /* 8*128 = 1024 */
    float*    s_log = (float*)smu;           /* aliases s_nx after GEMM (32*164 <= 8320) */

    const uint32_t wbase_u32 = smem_u32(s_wb);

    const int tid   = threadIdx.x;
    const int lane  = tid & 31;
    const int warp  = tid >> 5;
    const int b     = blockIdx.x / CHUNKS;
    const int chunk = blockIdx.x % CHUNKS;
    const int n0    = chunk * TILE_N;

    /* kick off W chunk 0 immediately — hides under LN x loads */
    load_chunk_async(wbase_u32, 0, 0, tid);

    for (int i = tid; i < DD; i += NTHREADS) { s_g[i] = ln_g[i]; s_b[i] = ln_b[i]; }
    if (tid < MM) s_bl[tid] = b_lin[tid];
    if (tid < HH) s_w2[tid] = W_t2[tid];
    const float bt2 = b_t2[0];

    __syncthreads();

    /* ---------------- Phase A: LayerNorm -> packed fp16 hi/lo ---------------- */
    for (int r = warp; r < TILE_N; r += 8) {
        const float4* xr = reinterpret_cast<const float4*>(
            x + ((size_t)(b * NN + n0 + r)) * DD);
        float4 v[4];
        float s = 0.f, sq = 0.f;
        #pragma unroll
        for (int q = 0; q < 4; q++) {
            v[q] = xr[lane + 32 * q];
            s  += v[q].x + v[q].y + v[q].z + v[q].w;
            sq += v[q].x * v[q].x + v[q].y * v[q].y + v[q].z * v[q].z + v[q].w * v[q].w;
        }
        #pragma unroll
        for (int o = 16; o > 0; o >>= 1) {
            s  += __shfl_xor_sync(0xffffffffu, s,  o);
            sq += __shfl_xor_sync(0xffffffffu, sq, o);
        }
        const float mu   = s * (1.0f / DD);
        const float var  = sq * (1.0f / DD) - mu * mu;
        const float rstd = rsqrtf(var + 1e-5f);
        #pragma unroll
        for (int q = 0; q < 4; q++) {
            const int k = (lane + 32 * q) * 4;
            float4 o4;
            o4.x = (v[q].x - mu) * rstd * s_g[k + 0] + s_b[k + 0];
            o4.y = (v[q].y - mu) * rstd * s_g[k + 1] + s_b[k + 1];
            o4.z = (v[q].z - mu) * rstd * s_g[k + 2] + s_b[k + 2];
            o4.w = (v[q].w - mu) * rstd * s_g[k + 3] + s_b[k + 3];
            const float hx = __half2float(__float2half_rn(o4.x));
            const float hy = __half2float(__float2half_rn(o4.y));
            const float hz = __half2float(__float2half_rn(o4.z));
            const float hw = __half2float(__float2half_rn(o4.w));
            uint2 hv, lv;
            hv.x = packh(o4.x, o4.y); hv.y = packh(o4.z, o4.w);
            lv.x = packh(o4.x - hx, o4.y - hy); lv.y = packh(o4.z - hz, o4.w - hw);
            const int wofs = r * NXW + (lane + 32 * q) * 2;
            *reinterpret_cast<uint2*>(s_nxh + wofs) = hv;
            *reinterpret_cast<uint2*>(s_nxl + wofs) = lv;
        }
    }

    /* ------------ Phase B: fp16 m16n8k16 GEMM, 2-term A split, pipelined ----- */
    const int wRow = warp >> 2;           /* 0..1 -> rows wRow*16 + [0,16) */
    const int wCol = warp & 3;            /* 0..3 -> cols wCol*40 + [0,40) */
    const int grp  = lane >> 2;           /* 0..7 */
    const int tig  = lane & 3;            /* 0..3 */

    float acc[5][4];
    #pragma unroll
    for (int j = 0; j < 5; j++)
        #pragma unroll
        for (int q = 0; q < 4; q++) acc[j][q] = 0.f;

    const int arow = wRow * 16 + grp;
    const uint32_t* ah_base = s_nxh + arow * NXW + tig;
    const uint32_t* al_base = s_nxl + arow * NXW + tig;

    CP_WAIT0();          /* chunk 0 landed */
    __syncthreads();     /* s_nx ready + chunk 0 visible */

    for (int kc = 0; kc < 16; kc++) {
        if (kc < 15) load_chunk_async(wbase_u32, kc + 1, (kc + 1) & 1, tid);

        const uint32_t* bh_buf = s_wb + (kc & 1) * (NC * WW);

        #pragma unroll
        for (int ks = 0; ks < 2; ks++) {
            const int ko = kc * 16 + ks * 8;
            uint32_t ah[4], al[4];
            const uint32_t* aph = ah_base + ko;
            const uint32_t* apl = al_base + ko;
            ah[0] = aph[0]; ah[1] = aph[8 * NXW]; ah[2] = aph[4]; ah[3] = aph[8 * NXW + 4];
            al[0] = apl[0]; al[1] = apl[8 * NXW]; al[2] = apl[4]; al[3] = apl[8 * NXW + 4];
            #pragma unroll
            for (int j = 0; j < 5; j++) {
                const int brow = (wCol * 40 + j * 8 + grp) * WW + ks * 8 + tig;
                uint32_t bh[2];
                bh[0] = bh_buf[brow]; bh[1] = bh_buf[brow + 4];
                mma_f16(acc[j], ah, bh);
                mma_f16(acc[j], al, bh);
            }
        }
        if (kc < 15) CP_WAIT0();
        __syncthreads();
    }

    /* write logits (+ b_lin for mode cols) to smem (aliases s_nx, synced above) */
    #pragma unroll
    for (int j = 0; j < 5; j++) {
        const int r0 = wRow * 16 + grp;
        const int c0 = wCol * 40 + j * 8 + 2 * tig;
        const float bb0 = (c0     < MM) ? s_bl[c0]     : 0.f;
        const float bb1 = (c0 + 1 < MM) ? s_bl[c0 + 1] : 0.f;
        s_log[r0 * LSTR + c0]           = acc[j][0] + bb0;
        s_log[r0 * LSTR + c0 + 1]       = acc[j][1] + bb1;
        s_log[(r0 + 8) * LSTR + c0]     = acc[j][2] + bb0;
        s_log[(r0 + 8) * LSTR + c0 + 1] = acc[j][3] + bb1;
    }
    __syncthreads();

    /* ---------------- Phase C/D: temperature + softmax (warp per row) ---- */
    float4 ps4 = make_float4(0.f, 0.f, 0.f, 0.f);
    for (int r = warp; r < TILE_N; r += 8) {
        float* lr = s_log + r * LSTR;

        const float tval = lr[MM + lane];
        const float gl = 0.5f * tval * (1.0f + erff(tval * 0.7071067811865476f));
        float cacc = gl * s_w2[lane];
        #pragma unroll
        for (int o = 16; o > 0; o >>= 1)
            cacc += __shfl_xor_sync(0xffffffffu, cacc, o);
        const float z   = cacc + bt2;
        const float sp  = (z > 20.f) ? z : log1pf(expf(z));
        const float tau = fminf(fmaxf(sp, 0.01f), 3.0f);
        const float itau = 1.0f / tau;
        const float ms = mass[(size_t)b * NN + n0 + r];

        float4 l4 = *reinterpret_cast<float4*>(lr + lane * 4);
        l4.x *= itau; l4.y *= itau; l4.z *= itau; l4.w *= itau;
        float mx = fmaxf(fmaxf(l4.x, l4.y), fmaxf(l4.z, l4.w));
        #pragma unroll
        for (int o = 16; o > 0; o >>= 1)
            mx = fmaxf(mx, __shfl_xor_sync(0xffffffffu, mx, o));
        float4 e;
        e.x = expf(l4.x - mx); e.y = expf(l4.y - mx);
        e.z = expf(l4.z - mx); e.w = expf(l4.w - mx);
        float ssum = e.x + e.y + e.z + e.w;
        #pragma unroll
        for (int o = 16; o > 0; o >>= 1)
            ssum += __shfl_xor_sync(0xffffffffu, ssum, o);
        const float inv = 1.0f / ssum;
        float4 p;
        p.x = e.x * inv; p.y = e.y * inv; p.z = e.z * inv; p.w = e.w * inv;

        *reinterpret_cast<float4*>(out + ((size_t)b * NN + n0 + r) * MM + lane * 4) = p;

        float4 pm;
        pm.x = p.x * ms; pm.y = p.y * ms; pm.z = p.z * ms; pm.w = p.w * ms;
        *reinterpret_cast<float4*>(lr + lane * 4) = pm;
        ps4.x += pm.x; ps4.y += pm.y; ps4.z += pm.z; ps4.w += pm.w;
    }

    s_ps[warp * MM + lane * 4 + 0] = ps4.x;
    s_ps[warp * MM + lane * 4 + 1] = ps4.y;
    s_ps[warp * MM + lane * 4 + 2] = ps4.z;
    s_ps[warp * MM + lane * 4 + 3] = ps4.w;
    __syncthreads();

    if (tid < MM) {
        float t = 0.f;
        #pragma unroll
        for (int w = 0; w < 8; w++) t += s_ps[w * MM + tid];
        g_partials[((size_t)b * MM + tid) * CHUNKS + chunk] = t;
    }

    /* ---------------- Phase E: transposed coalesced write of trial_in_t -- */
    const size_t off1 = (size_t)BB * NN * MM;
    #pragma unroll
    for (int it = 0; it < (TILE_N * MM) / NTHREADS; it++) {
        const int idx = it * NTHREADS + tid;
        const int m  = idx >> 5;
        const int nl = idx & 31;
        out[off1 + ((size_t)b * MM + m) * NN + n0 + nl] = s_log[nl * LSTR + m];
    }
}

__global__ void norm_kernel(float* __restrict__ out)
{
    __shared__ float red[256];
    const int idx = blockIdx.x;   /* b*M + m */
    const int tid = threadIdx.x;
    const float* p = g_partials + (size_t)idx * CHUNKS;
    float s = 0.f;
    for (int k = tid; k < CHUNKS; k += 256) s += p[k];
    red[tid] = s;
    __syncthreads();
    for (int o = 128; o > 0; o >>= 1) {
        if (tid < o) red[tid] += red[tid + o];
        __syncthreads();
    }
    if (tid == 0)
        out[(size_t)2 * BB * NN * MM + idx] = 1.0f / (red[0] + 1e-6f);
}

extern "C" void kernel_launch(void* const* d_in, const int* in_sizes, int n_in,
                              void* d_out, int out_size)
{
    const float* x     = (const float*)d_in[0];
    const float* mass  = (const float*)d_in[1];
    const float* ln_g  = (const float*)d_in[2];
    const float* ln_b  = (const float*)d_in[3];
    const float* W_lin = (const float*)d_in[4];
    const float* b_lin = (const float*)d_in[5];
    const float* W_t1  = (const float*)d_in[6];
    const float* W_t2  = (const float*)d_in[7];
    const float* b_t2  = (const float*)d_in[8];
    float* out = (float*)d_out;

    prep_w<<<NC, 256>>>(W_lin, W_t1);

    const int smem_bytes = (23040 + DD + DD + MM + HH + 8 * 128) * 4;  /* ~101 KB */
    cudaFuncSetAttribute(fused_kernel,
                         cudaFuncAttributeMaxDynamicSharedMemorySize, smem_bytes);

    fused_kernel<<<BB * CHUNKS, NTHREADS, smem_bytes>>>(
        x, mass, ln_g, ln_b, b_lin, W_t2, b_t2, out);
    norm_kernel<<<BB * MM, 256>>>(out);
}

// round 7
// speedup vs baseline: 3.6149x; 1.3434x over previous
#include <cuda_runtime.h>
#include <cuda_fp16.h>
#include <math.h>
#include <stdint.h>
#include <string.h>

#define BB 2
#define NN 65536
#define DD 512
#define MM 128
#define HH 32
#define TILE_N 32
#define CHUNKS (NN / TILE_N)   /* 2048 */
#define NC (MM + HH)           /* 160  */
#define NXW 260                /* u32 words per s_nx row (256 + 4 pad) */
#define WW  20                 /* u32 words per s_w chunk row (16 + 4 pad) */
#define LSTR 164               /* logits smem row stride (160 + 4 pad) */
#define NTHREADS 256

/* Deterministic scratch (no device-side allocation). */
__device__ float    g_partials[BB * MM * CHUNKS];
__device__ uint32_t g_w[NC * 256];   /* packed fp16x2, [row][k/2] */

__device__ __forceinline__ uint32_t smem_u32(const void* p)
{
    uint32_t a;
    asm("{ .reg .u64 t; cvta.to.shared.u64 t, %1; cvt.u32.u64 %0, t; }"
        : "=r"(a) : "l"(p));
    return a;
}

__device__ __forceinline__ uint32_t packh(float a, float b)
{
    __half2 t;
    t.x = __float2half_rn(a);
    t.y = __float2half_rn(b);
    uint32_t r;
    memcpy(&r, &t, 4);
    return r;
}

__device__ __forceinline__ void mma_f16(float* c, const uint32_t* a, const uint32_t* b)
{
    asm volatile(
        "mma.sync.aligned.m16n8k16.row.col.f32.f16.f16.f32 "
        "{%0,%1,%2,%3}, {%4,%5,%6,%7}, {%8,%9}, {%0,%1,%2,%3};"
        : "+f"(c[0]), "+f"(c[1]), "+f"(c[2]), "+f"(c[3])
        : "r"(a[0]), "r"(a[1]), "r"(a[2]), "r"(a[3]), "r"(b[0]), "r"(b[1]));
}

__device__ __forceinline__ void cp16(uint32_t dst, const uint32_t* src)
{
    asm volatile("cp.async.cg.shared.global [%0], [%1], 16;"
                 :: "r"(dst), "l"(__cvta_generic_to_global(src)) : "memory");
}
#define CP_COMMIT() asm volatile("cp.async.commit_group;" ::: "memory")
#define CP_WAIT0()  asm volatile("cp.async.wait_group 0;" ::: "memory")

/* One-time W convert: fp32 -> fp16 packed pairs. */
__global__ void prep_w(const float* __restrict__ W_lin, const float* __restrict__ W_t1)
{
    const int idx = blockIdx.x * 256 + threadIdx.x;   /* 0 .. 160*256-1 */
    if (idx >= NC * 256) return;
    const int row = idx >> 8;
    const int w   = idx & 255;
    const float* src = (row < MM) ? (W_lin + (size_t)row * DD)
                                  : (W_t1 + (size_t)(row - MM) * DD);
    g_w[idx] = packh(src[2 * w], src[2 * w + 1]);
}

/* Async copy of W chunk kc (640 x 16B) into buffer buf. */
__device__ __forceinline__ void load_chunk_async(uint32_t wbase_u32, int kc, int buf, int tid)
{
    const uint32_t dbase = wbase_u32 + buf * (NC * WW * 4);
    #pragma unroll
    for (int s = 0; s < 3; s++) {
        const int idx = tid + s * NTHREADS;
        if (idx < 640) {
            const int row = idx >> 2;
            const int q   = idx & 3;
            cp16(dbase + (row * WW + q * 4) * 4, g_w + row * 256 + kc * 16 + q * 4);
        }
    }
    CP_COMMIT();
}

__global__ void __launch_bounds__(NTHREADS, 3)
fused_kernel(const float* __restrict__ x, const float* __restrict__ mass,
             const float* __restrict__ ln_g, const float* __restrict__ ln_b,
             const float* __restrict__ b_lin, const float* __restrict__ W_t2,
             const float* __restrict__ b_t2, float* __restrict__ out)
{
    extern __shared__ uint32_t smu[];
    uint32_t* s_nxh = smu;                   /* 32*260 = 8320 */
    uint32_t* s_wb  = smu + 8320;            /* 2 bufs x 160*20 = 6400 */
    float*    s_g   = (float*)(smu + 14720); /* 512 */
    float*    s_b   = s_g + DD;              /* 512 */
    float*    s_bl  = s_b + DD;              /* 128 */
    float*    s_w2  = s_bl + MM;             /* 32  */
    float*    s_ps  = s_w2 + HH;             /* 8*128 = 1024 */
    float*    s_log = (float*)smu;           /* aliases s_nx after GEMM (32*164 <= 8320) */

    const uint32_t wbase_u32 = smem_u32(s_wb);

    const int tid   = threadIdx.x;
    const int lane  = tid & 31;
    const int warp  = tid >> 5;
    const int b     = blockIdx.x / CHUNKS;
    const int chunk = blockIdx.x % CHUNKS;
    const int n0    = chunk * TILE_N;

    /* kick off W chunk 0 immediately — hides under LN x loads */
    load_chunk_async(wbase_u32, 0, 0, tid);

    for (int i = tid; i < DD; i += NTHREADS) { s_g[i] = ln_g[i]; s_b[i] = ln_b[i]; }
    if (tid < MM) s_bl[tid] = b_lin[tid];
    if (tid < HH) s_w2[tid] = W_t2[tid];
    const float bt2 = b_t2[0];

    __syncthreads();

    /* ---------------- Phase A: LayerNorm -> packed fp16 ---------------- */
    for (int r = warp; r < TILE_N; r += 8) {
        const float4* xr = reinterpret_cast<const float4*>(
            x + ((size_t)(b * NN + n0 + r)) * DD);
        float4 v[4];
        float s = 0.f, sq = 0.f;
        #pragma unroll
        for (int q = 0; q < 4; q++) {
            v[q] = xr[lane + 32 * q];
            s  += v[q].x + v[q].y + v[q].z + v[q].w;
            sq += v[q].x * v[q].x + v[q].y * v[q].y + v[q].z * v[q].z + v[q].w * v[q].w;
        }
        #pragma unroll
        for (int o = 16; o > 0; o >>= 1) {
            s  += __shfl_xor_sync(0xffffffffu, s,  o);
            sq += __shfl_xor_sync(0xffffffffu, sq, o);
        }
        const float mu   = s * (1.0f / DD);
        const float var  = sq * (1.0f / DD) - mu * mu;
        const float rstd = rsqrtf(var + 1e-5f);
        #pragma unroll
        for (int q = 0; q < 4; q++) {
            const int k = (lane + 32 * q) * 4;
            float4 o4;
            o4.x = (v[q].x - mu) * rstd * s_g[k + 0] + s_b[k + 0];
            o4.y = (v[q].y - mu) * rstd * s_g[k + 1] + s_b[k + 1];
            o4.z = (v[q].z - mu) * rstd * s_g[k + 2] + s_b[k + 2];
            o4.w = (v[q].w - mu) * rstd * s_g[k + 3] + s_b[k + 3];
            uint2 hv;
            hv.x = packh(o4.x, o4.y); hv.y = packh(o4.z, o4.w);
            const int wofs = r * NXW + (lane + 32 * q) * 2;
            *reinterpret_cast<uint2*>(s_nxh + wofs) = hv;
        }
    }

    /* ------------ Phase B: fp16 m16n8k16 GEMM, pipelined ----- */
    const int wRow = warp >> 2;           /* 0..1 -> rows wRow*16 + [0,16) */
    const int wCol = warp & 3;            /* 0..3 -> cols wCol*40 + [0,40) */
    const int grp  = lane >> 2;           /* 0..7 */
    const int tig  = lane & 3;            /* 0..3 */

    float acc[5][4];
    #pragma unroll
    for (int j = 0; j < 5; j++)
        #pragma unroll
        for (int q = 0; q < 4; q++) acc[j][q] = 0.f;

    const int arow = wRow * 16 + grp;
    const uint32_t* ah_base = s_nxh + arow * NXW + tig;

    CP_WAIT0();          /* chunk 0 landed */
    __syncthreads();     /* s_nx ready + chunk 0 visible */

    for (int kc = 0; kc < 16; kc++) {
        if (kc < 15) load_chunk_async(wbase_u32, kc + 1, (kc + 1) & 1, tid);

        const uint32_t* bh_buf = s_wb + (kc & 1) * (NC * WW);

        #pragma unroll
        for (int ks = 0; ks < 2; ks++) {
            const int ko = kc * 16 + ks * 8;
            uint32_t ah[4];
            const uint32_t* aph = ah_base + ko;
            ah[0] = aph[0]; ah[1] = aph[8 * NXW]; ah[2] = aph[4]; ah[3] = aph[8 * NXW + 4];
            #pragma unroll
            for (int j = 0; j < 5; j++) {
                const int brow = (wCol * 40 + j * 8 + grp) * WW + ks * 8 + tig;
                uint32_t bh[2];
                bh[0] = bh_buf[brow]; bh[1] = bh_buf[brow + 4];
                mma_f16(acc[j], ah, bh);
            }
        }
        if (kc < 15) CP_WAIT0();
        __syncthreads();
    }

    /* write logits (+ b_lin for mode cols) to smem (aliases s_nx, synced above) */
    #pragma unroll
    for (int j = 0; j < 5; j++) {
        const int r0 = wRow * 16 + grp;
        const int c0 = wCol * 40 + j * 8 + 2 * tig;
        const float bb0 = (c0     < MM) ? s_bl[c0]     : 0.f;
        const float bb1 = (c0 + 1 < MM) ? s_bl[c0 + 1] : 0.f;
        s_log[r0 * LSTR + c0]           = acc[j][0] + bb0;
        s_log[r0 * LSTR + c0 + 1]       = acc[j][1] + bb1;
        s_log[(r0 + 8) * LSTR + c0]     = acc[j][2] + bb0;
        s_log[(r0 + 8) * LSTR + c0 + 1] = acc[j][3] + bb1;
    }
    __syncthreads();

    /* ---------------- Phase C/D: temperature + softmax (warp per row) ---- */
    float4 ps4 = make_float4(0.f, 0.f, 0.f, 0.f);
    for (int r = warp; r < TILE_N; r += 8) {
        float* lr = s_log + r * LSTR;

        const float tval = lr[MM + lane];
        const float gl = 0.5f * tval * (1.0f + erff(tval * 0.7071067811865476f));
        float cacc = gl * s_w2[lane];
        #pragma unroll
        for (int o = 16; o > 0; o >>= 1)
            cacc += __shfl_xor_sync(0xffffffffu, cacc, o);
        const float z   = cacc + bt2;
        const float sp  = (z > 20.f) ? z : log1pf(expf(z));
        const float tau = fminf(fmaxf(sp, 0.01f), 3.0f);
        const float itau = 1.0f / tau;
        const float ms = mass[(size_t)b * NN + n0 + r];

        float4 l4 = *reinterpret_cast<float4*>(lr + lane * 4);
        l4.x *= itau; l4.y *= itau; l4.z *= itau; l4.w *= itau;
        float mx = fmaxf(fmaxf(l4.x, l4.y), fmaxf(l4.z, l4.w));
        #pragma unroll
        for (int o = 16; o > 0; o >>= 1)
            mx = fmaxf(mx, __shfl_xor_sync(0xffffffffu, mx, o));
        float4 e;
        e.x = expf(l4.x - mx); e.y = expf(l4.y - mx);
        e.z = expf(l4.z - mx); e.w = expf(l4.w - mx);
        float ssum = e.x + e.y + e.z + e.w;
        #pragma unroll
        for (int o = 16; o > 0; o >>= 1)
            ssum += __shfl_xor_sync(0xffffffffu, ssum, o);
        const float inv = 1.0f / ssum;
        float4 p;
        p.x = e.x * inv; p.y = e.y * inv; p.z = e.z * inv; p.w = e.w * inv;

        *reinterpret_cast<float4*>(out + ((size_t)b * NN + n0 + r) * MM + lane * 4) = p;

        float4 pm;
        pm.x = p.x * ms; pm.y = p.y * ms; pm.z = p.z * ms; pm.w = p.w * ms;
        *reinterpret_cast<float4*>(lr + lane * 4) = pm;
        ps4.x += pm.x; ps4.y += pm.y; ps4.z += pm.z; ps4.w += pm.w;
    }

    s_ps[warp * MM + lane * 4 + 0] = ps4.x;
    s_ps[warp * MM + lane * 4 + 1] = ps4.y;
    s_ps[warp * MM + lane * 4 + 2] = ps4.z;
    s_ps[warp * MM + lane * 4 + 3] = ps4.w;
    __syncthreads();

    if (tid < MM) {
        float t = 0.f;
        #pragma unroll
        for (int w = 0; w < 8; w++) t += s_ps[w * MM + tid];
        g_partials[((size_t)b * MM + tid) * CHUNKS + chunk] = t;
    }

    /* ---------------- Phase E: transposed coalesced write of trial_in_t -- */
    const size_t off1 = (size_t)BB * NN * MM;
    #pragma unroll
    for (int it = 0; it < (TILE_N * MM) / NTHREADS; it++) {
        const int idx = it * NTHREADS + tid;
        const int m  = idx >> 5;
        const int nl = idx & 31;
        out[off1 + ((size_t)b * MM + m) * NN + n0 + nl] = s_log[nl * LSTR + m];
    }
}

__global__ void norm_kernel(float* __restrict__ out)
{
    __shared__ float red[256];
    const int idx = blockIdx.x;   /* b*M + m */
    const int tid = threadIdx.x;
    const float* p = g_partials + (size_t)idx * CHUNKS;
    float s = 0.f;
    for (int k = tid; k < CHUNKS; k += 256) s += p[k];
    red[tid] = s;
    __syncthreads();
    for (int o = 128; o > 0; o >>= 1) {
        if (tid < o) red[tid] += red[tid + o];
        __syncthreads();
    }
    if (tid == 0)
        out[(size_t)2 * BB * NN * MM + idx] = 1.0f / (red[0] + 1e-6f);
}

extern "C" void kernel_launch(void* const* d_in, const int* in_sizes, int n_in,
                              void* d_out, int out_size)
{
    const float* x     = (const float*)d_in[0];
    const float* mass  = (const float*)d_in[1];
    const float* ln_g  = (const float*)d_in[2];
    const float* ln_b  = (const float*)d_in[3];
    const float* W_lin = (const float*)d_in[4];
    const float* b_lin = (const float*)d_in[5];
    const float* W_t1  = (const float*)d_in[6];
    const float* W_t2  = (const float*)d_in[7];
    const float* b_t2  = (const float*)d_in[8];
    float* out = (float*)d_out;

    prep_w<<<NC, 256>>>(W_lin, W_t1);

    const int smem_bytes = (14720 + DD + DD + MM + HH + 8 * 128) * 4;  /* ~67 KB */
    cudaFuncSetAttribute(fused_kernel,
                         cudaFuncAttributeMaxDynamicSharedMemorySize, smem_bytes);

    fused_kernel<<<BB * CHUNKS, NTHREADS, smem_bytes>>>(
        x, mass, ln_g, ln_b, b_lin, W_t2, b_t2, out);
    norm_kernel<<<BB * MM, 256>>>(out);
}

// round 8
// speedup vs baseline: 3.8379x; 1.0617x over previous
#include <cuda_runtime.h>
#include <cuda_fp16.h>
#include <math.h>
#include <stdint.h>
#include <string.h>

#define BB 2
#define NN 65536
#define DD 512
#define MM 128
#define HH 32
#define TILE_N 64
#define CHUNKS (NN / TILE_N)   /* 1024 */
#define NC (MM + HH)           /* 160  */
#define NXW 260                /* u32 words per s_nx row (256 + 4 pad) */
#define WW  20                 /* u32 words per s_w chunk row (16 + 4 pad) */
#define LSTR 164               /* logits smem row stride (160 + 4 pad) */
#define NTHREADS 512

/* Deterministic scratch (no device-side allocation). */
__device__ float    g_partials[BB * MM * CHUNKS];
__device__ uint32_t g_w[NC * 256];   /* packed fp16x2, [row][k/2] */

__device__ __forceinline__ uint32_t smem_u32(const void* p)
{
    uint32_t a;
    asm("{ .reg .u64 t; cvta.to.shared.u64 t, %1; cvt.u32.u64 %0, t; }"
        : "=r"(a) : "l"(p));
    return a;
}

__device__ __forceinline__ uint32_t packh(float a, float b)
{
    __half2 t;
    t.x = __float2half_rn(a);
    t.y = __float2half_rn(b);
    uint32_t r;
    memcpy(&r, &t, 4);
    return r;
}

__device__ __forceinline__ void mma_f16(float* c, const uint32_t* a, const uint32_t* b)
{
    asm volatile(
        "mma.sync.aligned.m16n8k16.row.col.f32.f16.f16.f32 "
        "{%0,%1,%2,%3}, {%4,%5,%6,%7}, {%8,%9}, {%0,%1,%2,%3};"
        : "+f"(c[0]), "+f"(c[1]), "+f"(c[2]), "+f"(c[3])
        : "r"(a[0]), "r"(a[1]), "r"(a[2]), "r"(a[3]), "r"(b[0]), "r"(b[1]));
}

__device__ __forceinline__ void cp16(uint32_t dst, const uint32_t* src)
{
    asm volatile("cp.async.cg.shared.global [%0], [%1], 16;"
                 :: "r"(dst), "l"(__cvta_generic_to_global(src)) : "memory");
}
#define CP_COMMIT() asm volatile("cp.async.commit_group;" ::: "memory")
#define CP_WAIT0()  asm volatile("cp.async.wait_group 0;" ::: "memory")

/* One-time W convert: fp32 -> fp16 packed pairs. */
__global__ void prep_w(const float* __restrict__ W_lin, const float* __restrict__ W_t1)
{
    const int idx = blockIdx.x * 256 + threadIdx.x;   /* 0 .. 160*256-1 */
    if (idx >= NC * 256) return;
    const int row = idx >> 8;
    const int w   = idx & 255;
    const float* src = (row < MM) ? (W_lin + (size_t)row * DD)
                                  : (W_t1 + (size_t)(row - MM) * DD);
    g_w[idx] = packh(src[2 * w], src[2 * w + 1]);
}

/* Async copy of W chunk kc (640 x 16B) into buffer buf. */
__device__ __forceinline__ void load_chunk_async(uint32_t wbase_u32, int kc, int buf, int tid)
{
    const uint32_t dbase = wbase_u32 + buf * (NC * WW * 4);
    #pragma unroll
    for (int s = 0; s < 2; s++) {
        const int idx = tid + s * NTHREADS;
        if (idx < 640) {
            const int row = idx >> 2;
            const int q   = idx & 3;
            cp16(dbase + (row * WW + q * 4) * 4, g_w + row * 256 + kc * 16 + q * 4);
        }
    }
    CP_COMMIT();
}

__global__ void __launch_bounds__(NTHREADS, 2)
fused_kernel(const float* __restrict__ x, const float* __restrict__ mass,
             const float* __restrict__ ln_g, const float* __restrict__ ln_b,
             const float* __restrict__ b_lin, const float* __restrict__ W_t2,
             const float* __restrict__ b_t2, float* __restrict__ out)
{
    extern __shared__ uint32_t smu[];
    uint32_t* s_nxh = smu;                   /* 64*260 = 16640 */
    uint32_t* s_wb  = smu + 16640;           /* 2 bufs x 160*20 = 6400 */
    float*    s_g   = (float*)(smu + 23040); /* 512 */
    float*    s_b   = s_g + DD;              /* 512 */
    float*    s_bl  = s_b + DD;              /* 128 */
    float*    s_w2  = s_bl + MM;             /* 32  */
    float*    s_ps  = s_w2 + HH;             /* 16*128 = 2048 */
    float*    s_log = (float*)smu;           /* aliases s_nx after GEMM (64*164 <= 16640) */

    const uint32_t wbase_u32 = smem_u32(s_wb);

    const int tid   = threadIdx.x;
    const int lane  = tid & 31;
    const int warp  = tid >> 5;
    const int b     = blockIdx.x / CHUNKS;
    const int chunk = blockIdx.x % CHUNKS;
    const int n0    = chunk * TILE_N;

    /* kick off W chunk 0 immediately — hides under LN x loads */
    load_chunk_async(wbase_u32, 0, 0, tid);

    for (int i = tid; i < DD; i += NTHREADS) { s_g[i] = ln_g[i]; s_b[i] = ln_b[i]; }
    if (tid < MM) s_bl[tid] = b_lin[tid];
    if (tid < HH) s_w2[tid] = W_t2[tid];
    const float bt2 = b_t2[0];

    __syncthreads();

    /* ---------------- Phase A: LayerNorm -> packed fp16 ---------------- */
    for (int r = warp; r < TILE_N; r += 16) {
        const float4* xr = reinterpret_cast<const float4*>(
            x + ((size_t)(b * NN + n0 + r)) * DD);
        float4 v[4];
        float s = 0.f, sq = 0.f;
        #pragma unroll
        for (int q = 0; q < 4; q++) {
            v[q] = xr[lane + 32 * q];
            s  += v[q].x + v[q].y + v[q].z + v[q].w;
            sq += v[q].x * v[q].x + v[q].y * v[q].y + v[q].z * v[q].z + v[q].w * v[q].w;
        }
        #pragma unroll
        for (int o = 16; o > 0; o >>= 1) {
            s  += __shfl_xor_sync(0xffffffffu, s,  o);
            sq += __shfl_xor_sync(0xffffffffu, sq, o);
        }
        const float mu   = s * (1.0f / DD);
        const float var  = sq * (1.0f / DD) - mu * mu;
        const float rstd = rsqrtf(var + 1e-5f);
        #pragma unroll
        for (int q = 0; q < 4; q++) {
            const int k = (lane + 32 * q) * 4;
            float4 o4;
            o4.x = (v[q].x - mu) * rstd * s_g[k + 0] + s_b[k + 0];
            o4.y = (v[q].y - mu) * rstd * s_g[k + 1] + s_b[k + 1];
            o4.z = (v[q].z - mu) * rstd * s_g[k + 2] + s_b[k + 2];
            o4.w = (v[q].w - mu) * rstd * s_g[k + 3] + s_b[k + 3];
            uint2 hv;
            hv.x = packh(o4.x, o4.y); hv.y = packh(o4.z, o4.w);
            const int wofs = r * NXW + (lane + 32 * q) * 2;
            *reinterpret_cast<uint2*>(s_nxh + wofs) = hv;
        }
    }

    /* ------------ Phase B: fp16 m16n8k16 GEMM, pipelined ----- */
    const int wRow = warp >> 2;           /* 0..3 -> rows wRow*16 + [0,16) */
    const int wCol = warp & 3;            /* 0..3 -> cols wCol*40 + [0,40) */
    const int grp  = lane >> 2;           /* 0..7 */
    const int tig  = lane & 3;            /* 0..3 */

    float acc[5][4];
    #pragma unroll
    for (int j = 0; j < 5; j++)
        #pragma unroll
        for (int q = 0; q < 4; q++) acc[j][q] = 0.f;

    const int arow = wRow * 16 + grp;
    const uint32_t* ah_base = s_nxh + arow * NXW + tig;

    CP_WAIT0();          /* chunk 0 landed */
    __syncthreads();     /* s_nx ready + chunk 0 visible */

    for (int kc = 0; kc < 16; kc++) {
        if (kc < 15) load_chunk_async(wbase_u32, kc + 1, (kc + 1) & 1, tid);

        const uint32_t* bh_buf = s_wb + (kc & 1) * (NC * WW);

        #pragma unroll
        for (int ks = 0; ks < 2; ks++) {
            const int ko = kc * 16 + ks * 8;
            uint32_t ah[4];
            const uint32_t* aph = ah_base + ko;
            ah[0] = aph[0]; ah[1] = aph[8 * NXW]; ah[2] = aph[4]; ah[3] = aph[8 * NXW + 4];
            #pragma unroll
            for (int j = 0; j < 5; j++) {
                const int brow = (wCol * 40 + j * 8 + grp) * WW + ks * 8 + tig;
                uint32_t bh[2];
                bh[0] = bh_buf[brow]; bh[1] = bh_buf[brow + 4];
                mma_f16(acc[j], ah, bh);
            }
        }
        if (kc < 15) CP_WAIT0();
        __syncthreads();
    }

    /* write logits (+ b_lin for mode cols) to smem (aliases s_nx, synced above) */
    #pragma unroll
    for (int j = 0; j < 5; j++) {
        const int r0 = wRow * 16 + grp;
        const int c0 = wCol * 40 + j * 8 + 2 * tig;
        const float bb0 = (c0     < MM) ? s_bl[c0]     : 0.f;
        const float bb1 = (c0 + 1 < MM) ? s_bl[c0 + 1] : 0.f;
        s_log[r0 * LSTR + c0]           = acc[j][0] + bb0;
        s_log[r0 * LSTR + c0 + 1]       = acc[j][1] + bb1;
        s_log[(r0 + 8) * LSTR + c0]     = acc[j][2] + bb0;
        s_log[(r0 + 8) * LSTR + c0 + 1] = acc[j][3] + bb1;
    }
    __syncthreads();

    /* ---------------- Phase C/D: temperature + softmax (warp per row) ---- */
    float4 ps4 = make_float4(0.f, 0.f, 0.f, 0.f);
    for (int r = warp; r < TILE_N; r += 16) {
        float* lr = s_log + r * LSTR;

        const float tval = lr[MM + lane];
        const float gl = 0.5f * tval * (1.0f + erff(tval * 0.7071067811865476f));
        float cacc = gl * s_w2[lane];
        #pragma unroll
        for (int o = 16; o > 0; o >>= 1)
            cacc += __shfl_xor_sync(0xffffffffu, cacc, o);
        const float z   = cacc + bt2;
        const float sp  = (z > 20.f) ? z : log1pf(__expf(z));
        const float tau = fminf(fmaxf(sp, 0.01f), 3.0f);
        const float itau = __fdividef(1.0f, tau);
        const float ms = mass[(size_t)b * NN + n0 + r];

        float4 l4 = *reinterpret_cast<float4*>(lr + lane * 4);
        l4.x *= itau; l4.y *= itau; l4.z *= itau; l4.w *= itau;
        float mx = fmaxf(fmaxf(l4.x, l4.y), fmaxf(l4.z, l4.w));
        #pragma unroll
        for (int o = 16; o > 0; o >>= 1)
            mx = fmaxf(mx, __shfl_xor_sync(0xffffffffu, mx, o));
        float4 e;
        e.x = __expf(l4.x - mx); e.y = __expf(l4.y - mx);
        e.z = __expf(l4.z - mx); e.w = __expf(l4.w - mx);
        float ssum = e.x + e.y + e.z + e.w;
        #pragma unroll
        for (int o = 16; o > 0; o >>= 1)
            ssum += __shfl_xor_sync(0xffffffffu, ssum, o);
        const float inv = __fdividef(1.0f, ssum);
        float4 p;
        p.x = e.x * inv; p.y = e.y * inv; p.z = e.z * inv; p.w = e.w * inv;

        *reinterpret_cast<float4*>(out + ((size_t)b * NN + n0 + r) * MM + lane * 4) = p;

        float4 pm;
        pm.x = p.x * ms; pm.y = p.y * ms; pm.z = p.z * ms; pm.w = p.w * ms;
        *reinterpret_cast<float4*>(lr + lane * 4) = pm;
        ps4.x += pm.x; ps4.y += pm.y; ps4.z += pm.z; ps4.w += pm.w;
    }

    s_ps[warp * MM + lane * 4 + 0] = ps4.x;
    s_ps[warp * MM + lane * 4 + 1] = ps4.y;
    s_ps[warp * MM + lane * 4 + 2] = ps4.z;
    s_ps[warp * MM + lane * 4 + 3] = ps4.w;
    __syncthreads();

    if (tid < MM) {
        float t = 0.f;
        #pragma unroll
        for (int w = 0; w < 16; w++) t += s_ps[w * MM + tid];
        g_partials[((size_t)b * MM + tid) * CHUNKS + chunk] = t;
    }

    /* ---------------- Phase E: transposed coalesced write of trial_in_t -- */
    const size_t off1 = (size_t)BB * NN * MM;
    #pragma unroll
    for (int it = 0; it < (TILE_N * MM) / NTHREADS; it++) {
        const int idx = it * NTHREADS + tid;
        const int m  = idx >> 6;
        const int nl = idx & 63;
        out[off1 + ((size_t)b * MM + m) * NN + n0 + nl] = s_log[nl * LSTR + m];
    }
}

__global__ void norm_kernel(float* __restrict__ out)
{
    __shared__ float red[256];
    const int idx = blockIdx.x;   /* b*M + m */
    const int tid = threadIdx.x;
    const float* p = g_partials + (size_t)idx * CHUNKS;
    float s = 0.f;
    for (int k = tid; k < CHUNKS; k += 256) s += p[k];
    red[tid] = s;
    __syncthreads();
    for (int o = 128; o > 0; o >>= 1) {
        if (tid < o) red[tid] += red[tid + o];
        __syncthreads();
    }
    if (tid == 0)
        out[(size_t)2 * BB * NN * MM + idx] = 1.0f / (red[0] + 1e-6f);
}

extern "C" void kernel_launch(void* const* d_in, const int* in_sizes, int n_in,
                              void* d_out, int out_size)
{
    const float* x     = (const float*)d_in[0];
    const float* mass  = (const float*)d_in[1];
    const float* ln_g  = (const float*)d_in[2];
    const float* ln_b  = (const float*)d_in[3];
    const float* W_lin = (const float*)d_in[4];
    const float* b_lin = (const float*)d_in[5];
    const float* W_t1  = (const float*)d_in[6];
    const float* W_t2  = (const float*)d_in[7];
    const float* b_t2  = (const float*)d_in[8];
    float* out = (float*)d_out;

    prep_w<<<NC, 256>>>(W_lin, W_t1);

    const int smem_bytes = (23040 + DD + DD + MM + HH + 16 * 128) * 4;  /* ~105 KB */
    cudaFuncSetAttribute(fused_kernel,
                         cudaFuncAttributeMaxDynamicSharedMemorySize, smem_bytes);

    fused_kernel<<<BB * CHUNKS, NTHREADS, smem_bytes>>>(
        x, mass, ln_g, ln_b, b_lin, W_t2, b_t2, out);
    norm_kernel<<<BB * MM, 256>>>(out);
}